// round 3
// baseline (speedup 1.0000x reference)
#include <cuda_runtime.h>

// ---------------------------------------------------------------------------
// EquivariantMessagePassing — GB300 sm_103a
//
// Factorization:
//   h_e = silu( A[row] + B[col] + dist_sq * Wx1[128,:] )        (A has bx1 baked in)
//   msg_x_e = h_e @ Wx2 + bx2           -> atomic scatter to out_x[col]
//   pos_upd = wpos[row] * rel_pos       -> atomic scatter to out_pos[col]
// where per-node precompute:
//   A[n] = x[n] @ Wx1[0:64,:] + bx1,  B[n] = x[n] @ Wx1[64:128,:]
//   wpos[n] = silu(x[n]@Wp1 + bp1) @ Wp2 + bp2
// ---------------------------------------------------------------------------

#define MAX_N 100000
#define F_DIM 64
#define H_DIM 128

// Scratch (module-load allocation, allowed)
__device__ float g_A[(size_t)MAX_N * H_DIM];     // 51.2 MB
__device__ float g_B[(size_t)MAX_N * H_DIM];     // 51.2 MB
__device__ float g_wpos[MAX_N];
__device__ int   g_idx_is64;                     // 1 if edge_index is int64

__device__ __forceinline__ float silu_f(float v) {
    return v / (1.0f + __expf(-v));
}

// ---------------------------------------------------------------------------
// Kernel 0: detect edge_index element width. If the buffer holds int64
// indices in [0,N), reading as int64 gives small values. If it holds int32,
// an int64 read packs two indices -> hi word nonzero almost surely.
// ---------------------------------------------------------------------------
__global__ void detect_idx_width(const long long* __restrict__ ei, int nCheck, long long nNodes)
{
    if (threadIdx.x == 0 && blockIdx.x == 0) {
        int is64 = 1;
        for (int i = 0; i < nCheck; i++) {
            long long v = ei[i];
            if (v < 0 || v >= nNodes) { is64 = 0; break; }
        }
        g_idx_is64 = is64;
    }
}

__device__ __forceinline__ void load_edge(const void* ei, int e, int E, int is64,
                                          int nNodes, int& r, int& c)
{
    long long rv, cv;
    if (is64) {
        rv = ((const long long*)ei)[e];
        cv = ((const long long*)ei)[(size_t)E + e];
    } else {
        rv = ((const int*)ei)[e];
        cv = ((const int*)ei)[(size_t)E + e];
    }
    // clamp: invalid -> sentinel (-1) so edge is skipped, never OOB
    r = (rv >= 0 && rv < nNodes) ? (int)rv : -1;
    c = (cv >= 0 && cv < nNodes) ? (int)cv : -1;
    if (r < 0) c = -1;
}

// ---------------------------------------------------------------------------
// Kernel 1: per-node precompute. 128 threads, 8 nodes/block.
// thread tid owns hidden column j = tid for all three matrices.
// ---------------------------------------------------------------------------
__global__ __launch_bounds__(128) void node_precompute(
    const float* __restrict__ x,
    const float* __restrict__ Wx1, const float* __restrict__ bx1,
    const float* __restrict__ Wp1, const float* __restrict__ bp1,
    const float* __restrict__ Wp2, const float* __restrict__ bp2,
    int nNodes)
{
    const int NPB = 8;
    __shared__ float xs[NPB * F_DIM];
    __shared__ float wpart[4][NPB];

    int n0  = blockIdx.x * NPB;
    int tid = threadIdx.x;

    // stage x for 8 nodes
    for (int i = tid; i < NPB * F_DIM; i += 128) {
        int node = n0 + (i >> 6);
        xs[i] = (node < nNodes) ? x[(size_t)n0 * F_DIM + i] : 0.0f;
    }
    __syncthreads();

    float accA[NPB], accB[NPB], accP[NPB];
#pragma unroll
    for (int m = 0; m < NPB; m++) { accA[m] = 0.f; accB[m] = 0.f; accP[m] = 0.f; }

    const float* wx1a = Wx1 + tid;                  // rows 0..63
    const float* wx1b = Wx1 + 64 * H_DIM + tid;     // rows 64..127
    const float* wp1c = Wp1 + tid;

#pragma unroll 4
    for (int k = 0; k < F_DIM; k++) {
        float w1 = wx1a[k * H_DIM];
        float w2 = wx1b[k * H_DIM];
        float wp = wp1c[k * H_DIM];
#pragma unroll
        for (int m = 0; m < NPB; m++) {
            float xv = xs[m * F_DIM + k];
            accA[m] = fmaf(xv, w1, accA[m]);
            accB[m] = fmaf(xv, w2, accB[m]);
            accP[m] = fmaf(xv, wp, accP[m]);
        }
    }

    float b1  = bx1[tid];
    float bp  = bp1[tid];
    float w2v = Wp2[tid];

#pragma unroll
    for (int m = 0; m < NPB; m++) {
        int node = n0 + m;
        if (node < nNodes) {
            g_A[(size_t)node * H_DIM + tid] = accA[m] + b1;
            g_B[(size_t)node * H_DIM + tid] = accB[m];
        }
        float hv = accP[m] + bp;
        float contrib = silu_f(hv) * w2v;
#pragma unroll
        for (int off = 16; off; off >>= 1)
            contrib += __shfl_xor_sync(0xffffffffu, contrib, off);
        if ((tid & 31) == 0) wpart[tid >> 5][m] = contrib;
    }
    __syncthreads();

    if (tid < NPB) {
        int node = n0 + tid;
        if (node < nNodes)
            g_wpos[node] = wpart[0][tid] + wpart[1][tid] + wpart[2][tid] + wpart[3][tid] + bp2[0];
    }
}

// ---------------------------------------------------------------------------
// Kernel 2: fused edge kernel. 256 threads, 128 edges/tile.
//   Phase A: assemble Hs[e][k] = silu(A[row]+B[col]+dsq*w128)  (smem)
//            + pos-branch atomics
//   Phase B: Hs[128x128] @ Ws[128x64] register-tiled SGEMM,
//            epilogue: += bx2, atomic scatter to out_x[col]
// ---------------------------------------------------------------------------
#define TILE_E 128

__global__ __launch_bounds__(256, 2) void edge_kernel(
    const float* __restrict__ pos,
    const void* __restrict__ ei,           // [2, E] (int32 or int64)
    const float* __restrict__ Wx1,         // for row 128 (dist_sq weights)
    const float* __restrict__ Wx2,         // [128, 64]
    const float* __restrict__ bx2,         // [64]
    float* __restrict__ outx,              // [N, 64]
    float* __restrict__ outpos,            // [N, 3]
    int E, int nNodes)
{
    extern __shared__ float sm[];
    float* Hs   = sm;                       // 128*128 floats (e-major, stride 128)
    float* Ws   = sm + TILE_E * H_DIM;      // 128*64
    float* w128 = Ws + H_DIM * F_DIM;       // 128
    float* bx2s = w128 + H_DIM;             // 64
    int*   colIx = (int*)(bx2s + F_DIM);    // 128

    int tid = threadIdx.x;
    int is64 = g_idx_is64;

    // stage weights
    for (int i = tid; i < (H_DIM * F_DIM) / 4; i += 256)
        ((float4*)Ws)[i] = ((const float4*)Wx2)[i];
    if (tid < H_DIM) w128[tid] = Wx1[H_DIM * H_DIM + tid]; // row index 128 of [129,128]
    if (tid < F_DIM) bx2s[tid] = bx2[tid];

    int blockBase = blockIdx.x * TILE_E;
    int warpId = tid >> 5, lane = tid & 31;

    // prefetch this warp's 16 edge indices (lanes 0..15)
    int myE = warpId * 16 + (lane & 15);
    int gE  = blockBase + myE;
    int rIdx = -1, cIdx = -1;
    if (lane < 16) {
        if (gE < E) load_edge(ei, gE, E, is64, nNodes, rIdx, cIdx);
        colIx[myE] = cIdx;
    }
    __syncthreads();   // weights + colIx visible

    // ------------------------- Phase A -------------------------
    for (int t = 0; t < 16; t++) {
        int row = __shfl_sync(0xffffffffu, rIdx, t);
        int col = __shfl_sync(0xffffffffu, cIdx, t);
        int eL  = warpId * 16 + t;
        float4 h4 = make_float4(0.f, 0.f, 0.f, 0.f);
        if (col >= 0) {
            // dist_sq via 3 lanes
            float d = 0.f;
            if (lane < 3) d = pos[row * 3 + lane] - pos[col * 3 + lane];
            float dd = d * d;
            dd += __shfl_xor_sync(0xffffffffu, dd, 1);
            dd += __shfl_xor_sync(0xffffffffu, dd, 2);
            float dsq = __shfl_sync(0xffffffffu, dd, 0);

            // pos scatter (3 atomics)
            if (lane < 3) {
                float wp = g_wpos[row];
                atomicAdd(&outpos[(size_t)col * 3 + lane], wp * d);
            }

            float4 a = ((const float4*)g_A)[(size_t)row * 32 + lane];
            float4 b = ((const float4*)g_B)[(size_t)col * 32 + lane];
            float4 w = ((const float4*)w128)[lane];
            h4.x = silu_f(a.x + b.x + dsq * w.x);
            h4.y = silu_f(a.y + b.y + dsq * w.y);
            h4.z = silu_f(a.z + b.z + dsq * w.z);
            h4.w = silu_f(a.w + b.w + dsq * w.w);
        }
        // conflict-free: quarter-warp covers all 32 banks
        ((float4*)(Hs + (size_t)eL * H_DIM))[lane] = h4;
    }
    __syncthreads();

    // ------------------------- Phase B: SGEMM -------------------------
    // 16x16 thread grid: trow owns 8 edges, tcol owns 4 outputs
    int tcol = tid & 15;
    int trow = tid >> 4;

    float acc[8][4];
#pragma unroll
    for (int r = 0; r < 8; r++)
#pragma unroll
        for (int c = 0; c < 4; c++) acc[r][c] = 0.f;

    const float*  HsBase = Hs + (size_t)trow * 8 * H_DIM;
    const float4* Ws4    = (const float4*)Ws;

#pragma unroll 2
    for (int k = 0; k < H_DIM; k += 4) {
        float4 b0 = Ws4[(k + 0) * 16 + tcol];
        float4 b1 = Ws4[(k + 1) * 16 + tcol];
        float4 b2 = Ws4[(k + 2) * 16 + tcol];
        float4 b3 = Ws4[(k + 3) * 16 + tcol];
#pragma unroll
        for (int r = 0; r < 8; r++) {
            float4 av = *(const float4*)&HsBase[r * H_DIM + k];
            acc[r][0] = fmaf(av.x, b0.x, acc[r][0]);
            acc[r][1] = fmaf(av.x, b0.y, acc[r][1]);
            acc[r][2] = fmaf(av.x, b0.z, acc[r][2]);
            acc[r][3] = fmaf(av.x, b0.w, acc[r][3]);
            acc[r][0] = fmaf(av.y, b1.x, acc[r][0]);
            acc[r][1] = fmaf(av.y, b1.y, acc[r][1]);
            acc[r][2] = fmaf(av.y, b1.z, acc[r][2]);
            acc[r][3] = fmaf(av.y, b1.w, acc[r][3]);
            acc[r][0] = fmaf(av.z, b2.x, acc[r][0]);
            acc[r][1] = fmaf(av.z, b2.y, acc[r][1]);
            acc[r][2] = fmaf(av.z, b2.z, acc[r][2]);
            acc[r][3] = fmaf(av.z, b2.w, acc[r][3]);
            acc[r][0] = fmaf(av.w, b3.x, acc[r][0]);
            acc[r][1] = fmaf(av.w, b3.y, acc[r][1]);
            acc[r][2] = fmaf(av.w, b3.z, acc[r][2]);
            acc[r][3] = fmaf(av.w, b3.w, acc[r][3]);
        }
    }

    // ------------------------- Epilogue: scatter -------------------------
    float4 bb = ((const float4*)bx2s)[tcol];
#pragma unroll
    for (int r = 0; r < 8; r++) {
        int eL  = trow * 8 + r;
        int col = colIx[eL];
        if (col >= 0) {
            float* dst = outx + (size_t)col * F_DIM + tcol * 4;
            atomicAdd(dst + 0, acc[r][0] + bb.x);
            atomicAdd(dst + 1, acc[r][1] + bb.y);
            atomicAdd(dst + 2, acc[r][2] + bb.z);
            atomicAdd(dst + 3, acc[r][3] + bb.w);
        }
    }
}

// ---------------------------------------------------------------------------
extern "C" void kernel_launch(void* const* d_in, const int* in_sizes, int n_in,
                              void* d_out, int out_size)
{
    const float* x   = (const float*)d_in[0];
    const float* pos = (const float*)d_in[1];
    const void*  ei  = d_in[2];
    const float* Wx1 = (const float*)d_in[3];
    const float* bx1 = (const float*)d_in[4];
    const float* Wx2 = (const float*)d_in[5];
    const float* bx2 = (const float*)d_in[6];
    const float* Wp1 = (const float*)d_in[7];
    const float* bp1 = (const float*)d_in[8];
    const float* Wp2 = (const float*)d_in[9];
    const float* bp2 = (const float*)d_in[10];

    int nNodes = in_sizes[0] / F_DIM;      // 100000
    int E      = in_sizes[2] / 2;          // 1000000

    float* outx   = (float*)d_out;                           // [N, 64]
    float* outpos = (float*)d_out + (size_t)nNodes * F_DIM;  // [N, 3]

    // zero outputs (poisoned by harness)
    cudaMemsetAsync(d_out, 0, sizeof(float) * (size_t)nNodes * (F_DIM + 3));

    // Kernel 0: index-width detection (reads at most first 32 int64 slots = 64 int32)
    int nCheck = (E < 64) ? E : 64;
    // ensure we never read past the int32 interpretation: nCheck int64 reads
    // touch 2*nCheck int32 slots <= 2E slots. Safe.
    detect_idx_width<<<1, 32>>>((const long long*)ei, nCheck / 2, (long long)nNodes);

    // Kernel 1: node precompute
    node_precompute<<<(nNodes + 7) / 8, 128>>>(x, Wx1, bx1, Wp1, bp1, Wp2, bp2, nNodes);

    // Kernel 2: fused edge kernel
    size_t shmem = sizeof(float) * (TILE_E * H_DIM + H_DIM * F_DIM + H_DIM + F_DIM)
                 + sizeof(int) * TILE_E;
    cudaFuncSetAttribute(edge_kernel, cudaFuncAttributeMaxDynamicSharedMemorySize, (int)shmem);
    edge_kernel<<<(E + TILE_E - 1) / TILE_E, 256, shmem>>>(
        pos, ei, Wx1, Wx2, bx2, outx, outpos, E, nNodes);
}

// round 4
// speedup vs baseline: 1.3259x; 1.3259x over previous
#include <cuda_runtime.h>
#include <cstdint>

// ---------------------------------------------------------------------------
// EquivariantMessagePassing — GB300 sm_103a — Round 4
//
// Factorization:
//   h_e = silu( A[row] + B[col] + dist_sq * Wx1[128,:] )   (A has bx1 baked in)
//   msg_x_e = h_e @ Wx2 + bx2    -> atomic scatter to out_x[col]
//   pos_upd = wpos[row]*rel_pos  -> atomic scatter to out_pos[col]
// Edge GEMM on tensor cores: mma.sync.m16n8k8.tf32 with hi/lo split (3 terms)
// under a consistent k-permutation so gathers are float4-contiguous and
// fragments are register-indexable.
// ---------------------------------------------------------------------------

#define MAX_N 100000
#define F_DIM 64
#define H_DIM 128

__device__ float  g_A[(size_t)MAX_N * H_DIM];     // 51.2 MB
__device__ float  g_B[(size_t)MAX_N * H_DIM];     // 51.2 MB
__device__ float  g_wpos[MAX_N];
__device__ int    g_idx_is64;
__device__ float4 g_Wfrag[16 * 8 * 32];           // [t][n][lane] = (b0hi,b0lo,b1hi,b1lo)

__device__ __forceinline__ float silu_f(float v) {
    return v / (1.0f + __expf(-v));
}

__device__ __forceinline__ unsigned tf32_rnd(float v) {
    unsigned r;
    asm("cvt.rna.tf32.f32 %0, %1;" : "=r"(r) : "f"(v));
    return r;
}

__device__ __forceinline__ void mma_tf32(float acc[4],
                                         unsigned a0, unsigned a1, unsigned a2, unsigned a3,
                                         unsigned b0, unsigned b1) {
    asm volatile(
        "mma.sync.aligned.m16n8k8.row.col.f32.tf32.tf32.f32 "
        "{%0,%1,%2,%3}, {%4,%5,%6,%7}, {%8,%9}, {%0,%1,%2,%3};"
        : "+f"(acc[0]), "+f"(acc[1]), "+f"(acc[2]), "+f"(acc[3])
        : "r"(a0), "r"(a1), "r"(a2), "r"(a3), "r"(b0), "r"(b1));
}

__device__ __forceinline__ void load_edge(const void* ei, int e, int E, int is64,
                                          int nNodes, int& r, int& c)
{
    long long rv, cv;
    if (is64) {
        rv = ((const long long*)ei)[e];
        cv = ((const long long*)ei)[(size_t)E + e];
    } else {
        rv = ((const int*)ei)[e];
        cv = ((const int*)ei)[(size_t)E + e];
    }
    r = (rv >= 0 && rv < nNodes) ? (int)rv : -1;
    c = (cv >= 0 && cv < nNodes) ? (int)cv : -1;
    if (r < 0) c = -1;
}

// ---------------------------------------------------------------------------
// Kernel 0: prep — edge-index width detection + W2 fragment pre-bake.
// Fragment k-permutation: actual k for slot (c=lane%4, reg half, t) is
//   k = c*32 + half*16 + t         (t = k-tile 0..15)
// g_Wfrag[(t*8+n)*32 + lane] = (hi(W2[k0][col]), lo, hi(W2[k1][col]), lo)
//   where k0 = c*32+t, k1 = k0+16, col = n*8 + (lane>>2)
// ---------------------------------------------------------------------------
__global__ void prep_kernel(const float* __restrict__ Wx2,
                            const long long* __restrict__ ei,
                            int nCheck, long long nNodes)
{
    int tid = threadIdx.x;
    if (tid == 0) {
        int is64 = 1;
        for (int i = 0; i < nCheck; i++) {
            long long v = ei[i];
            if (v < 0 || v >= nNodes) { is64 = 0; break; }
        }
        g_idx_is64 = is64;
    }
    for (int i = tid; i < 16 * 8 * 32; i += blockDim.x) {
        int lane = i & 31;
        int n    = (i >> 5) & 7;
        int t    = i >> 8;
        int c    = lane & 3;
        int gid  = lane >> 2;
        int col  = n * 8 + gid;
        int k0   = c * 32 + t;
        int k1   = k0 + 16;
        float w0 = Wx2[k0 * F_DIM + col];
        float w1 = Wx2[k1 * F_DIM + col];
        unsigned h0 = tf32_rnd(w0);
        unsigned h1 = tf32_rnd(w1);
        float l0 = w0 - __uint_as_float(h0);
        float l1 = w1 - __uint_as_float(h1);
        g_Wfrag[i] = make_float4(__uint_as_float(h0),
                                 __uint_as_float(tf32_rnd(l0)),
                                 __uint_as_float(h1),
                                 __uint_as_float(tf32_rnd(l1)));
    }
}

// ---------------------------------------------------------------------------
// Kernel 1: per-node precompute (+ output zeroing). 128 threads, 8 nodes/block.
// ---------------------------------------------------------------------------
__global__ __launch_bounds__(128) void node_precompute(
    const float* __restrict__ x,
    const float* __restrict__ Wx1, const float* __restrict__ bx1,
    const float* __restrict__ Wp1, const float* __restrict__ bp1,
    const float* __restrict__ Wp2, const float* __restrict__ bp2,
    float* __restrict__ out0, size_t zeroCount,
    int nNodes)
{
    const int NPB = 8;
    __shared__ float xs[NPB * F_DIM];
    __shared__ float wpart[4][NPB];

    int n0  = blockIdx.x * NPB;
    int tid = threadIdx.x;

    // zero the output buffer (grid-stride)
    for (size_t i = (size_t)blockIdx.x * blockDim.x + tid; i < zeroCount;
         i += (size_t)gridDim.x * blockDim.x)
        out0[i] = 0.0f;

    // stage x for 8 nodes
    for (int i = tid; i < NPB * F_DIM; i += 128) {
        int node = n0 + (i >> 6);
        xs[i] = (node < nNodes) ? x[(size_t)n0 * F_DIM + i] : 0.0f;
    }
    __syncthreads();

    float accA[NPB], accB[NPB], accP[NPB];
#pragma unroll
    for (int m = 0; m < NPB; m++) { accA[m] = 0.f; accB[m] = 0.f; accP[m] = 0.f; }

    const float* wx1a = Wx1 + tid;
    const float* wx1b = Wx1 + 64 * H_DIM + tid;
    const float* wp1c = Wp1 + tid;

#pragma unroll 4
    for (int k = 0; k < F_DIM; k++) {
        float w1 = wx1a[k * H_DIM];
        float w2 = wx1b[k * H_DIM];
        float wp = wp1c[k * H_DIM];
#pragma unroll
        for (int m = 0; m < NPB; m++) {
            float xv = xs[m * F_DIM + k];
            accA[m] = fmaf(xv, w1, accA[m]);
            accB[m] = fmaf(xv, w2, accB[m]);
            accP[m] = fmaf(xv, wp, accP[m]);
        }
    }

    float b1  = bx1[tid];
    float bp  = bp1[tid];
    float w2v = Wp2[tid];

#pragma unroll
    for (int m = 0; m < NPB; m++) {
        int node = n0 + m;
        if (node < nNodes) {
            g_A[(size_t)node * H_DIM + tid] = accA[m] + b1;
            g_B[(size_t)node * H_DIM + tid] = accB[m];
        }
        float hv = accP[m] + bp;
        float contrib = silu_f(hv) * w2v;
#pragma unroll
        for (int off = 16; off; off >>= 1)
            contrib += __shfl_xor_sync(0xffffffffu, contrib, off);
        if ((tid & 31) == 0) wpart[tid >> 5][m] = contrib;
    }
    __syncthreads();

    if (tid < NPB) {
        int node = n0 + tid;
        if (node < nNodes)
            g_wpos[node] = wpart[0][tid] + wpart[1][tid] + wpart[2][tid] + wpart[3][tid] + bp2[0];
    }
}

// ---------------------------------------------------------------------------
// Kernel 2: edge kernel, tensor-core GEMM. 128 threads (4 warps), 64 edges/block.
// Each warp owns 16 edges: gathers h into registers (k-permuted), runs
// 16 k-tiles x 8 n-tiles x 3 split-terms of m16n8k8.tf32, scatters via RED.
// No shared memory, no block sync.
// ---------------------------------------------------------------------------
__global__ __launch_bounds__(128) void edge_kernel(
    const float* __restrict__ pos,
    const void*  __restrict__ ei,
    const float* __restrict__ Wx1,      // row 128 = dist_sq weights
    const float* __restrict__ bx2,
    float* __restrict__ outx,           // [N, 64]
    float* __restrict__ outpos,         // [N, 3]
    int E, int nNodes)
{
    const unsigned FULL = 0xffffffffu;
    int tid   = threadIdx.x;
    int lane  = tid & 31;
    int warp  = tid >> 5;
    int warpE = blockIdx.x * 64 + warp * 16;
    int is64  = g_idx_is64;

    // ---- lanes 0..15: per-edge index load, dist, pos-branch scatter ----
    int   rIdx = -1, cIdx = -1;
    float dsq  = 0.f;
    if (lane < 16) {
        int gE = warpE + lane;
        if (gE < E) load_edge(ei, gE, E, is64, nNodes, rIdx, cIdx);
        if (cIdx >= 0) {
            float dx = pos[rIdx * 3 + 0] - pos[cIdx * 3 + 0];
            float dy = pos[rIdx * 3 + 1] - pos[cIdx * 3 + 1];
            float dz = pos[rIdx * 3 + 2] - pos[cIdx * 3 + 2];
            dsq = dx * dx + dy * dy + dz * dz;
            float wp = g_wpos[rIdx];
            atomicAdd(&outpos[(size_t)cIdx * 3 + 0], wp * dx);
            atomicAdd(&outpos[(size_t)cIdx * 3 + 1], wp * dy);
            atomicAdd(&outpos[(size_t)cIdx * 3 + 2], wp * dz);
        }
    }

    int gidA = lane >> 2;          // edge (m-row) 0..7
    int gidB = gidA + 8;           // edge (m-row) 8..15
    int c    = lane & 3;           // tig

    int   rowA = __shfl_sync(FULL, rIdx, gidA);
    int   colA = __shfl_sync(FULL, cIdx, gidA);
    float dsqA = __shfl_sync(FULL, dsq,  gidA);
    int   rowB = __shfl_sync(FULL, rIdx, gidB);
    int   colB = __shfl_sync(FULL, cIdx, gidB);
    float dsqB = __shfl_sync(FULL, dsq,  gidB);

    // ---- gather + activation into registers (k = c*32 + 0..31) ----
    float hA[32], hB[32];
    const float* w128 = Wx1 + H_DIM * H_DIM;   // row 128 of [129,128]

#pragma unroll
    for (int j = 0; j < 8; j++) {
        int k = c * 32 + 4 * j;
        float4 w4 = *(const float4*)(w128 + k);
        if (colA >= 0) {
            float4 a4 = *(const float4*)(g_A + (size_t)rowA * H_DIM + k);
            float4 b4 = *(const float4*)(g_B + (size_t)colA * H_DIM + k);
            hA[4 * j + 0] = silu_f(a4.x + b4.x + dsqA * w4.x);
            hA[4 * j + 1] = silu_f(a4.y + b4.y + dsqA * w4.y);
            hA[4 * j + 2] = silu_f(a4.z + b4.z + dsqA * w4.z);
            hA[4 * j + 3] = silu_f(a4.w + b4.w + dsqA * w4.w);
        } else {
            hA[4 * j + 0] = 0.f; hA[4 * j + 1] = 0.f;
            hA[4 * j + 2] = 0.f; hA[4 * j + 3] = 0.f;
        }
        if (colB >= 0) {
            float4 a4 = *(const float4*)(g_A + (size_t)rowB * H_DIM + k);
            float4 b4 = *(const float4*)(g_B + (size_t)colB * H_DIM + k);
            hB[4 * j + 0] = silu_f(a4.x + b4.x + dsqB * w4.x);
            hB[4 * j + 1] = silu_f(a4.y + b4.y + dsqB * w4.y);
            hB[4 * j + 2] = silu_f(a4.z + b4.z + dsqB * w4.z);
            hB[4 * j + 3] = silu_f(a4.w + b4.w + dsqB * w4.w);
        } else {
            hB[4 * j + 0] = 0.f; hB[4 * j + 1] = 0.f;
            hB[4 * j + 2] = 0.f; hB[4 * j + 3] = 0.f;
        }
    }

    // ---- tensor-core GEMM: D[16 edges][64 cols] ----
    float acc[8][4];
#pragma unroll
    for (int n = 0; n < 8; n++)
#pragma unroll
        for (int q = 0; q < 4; q++) acc[n][q] = 0.f;

    const float4* wf = g_Wfrag;

#pragma unroll
    for (int t = 0; t < 16; t++) {
        // fragment slots: a0=(gidA,k c*32+t) a1=(gidB,same) a2=(gidA,k+16) a3=(gidB,k+16)
        float a0 = hA[t],      a1 = hB[t];
        float a2 = hA[16 + t], a3 = hB[16 + t];
        unsigned ah0 = tf32_rnd(a0), ah1 = tf32_rnd(a1);
        unsigned ah2 = tf32_rnd(a2), ah3 = tf32_rnd(a3);
        unsigned al0 = tf32_rnd(a0 - __uint_as_float(ah0));
        unsigned al1 = tf32_rnd(a1 - __uint_as_float(ah1));
        unsigned al2 = tf32_rnd(a2 - __uint_as_float(ah2));
        unsigned al3 = tf32_rnd(a3 - __uint_as_float(ah3));
#pragma unroll
        for (int n = 0; n < 8; n++) {
            float4 b = wf[(t * 8 + n) * 32 + lane];
            unsigned b0h = __float_as_uint(b.x), b0l = __float_as_uint(b.y);
            unsigned b1h = __float_as_uint(b.z), b1l = __float_as_uint(b.w);
            mma_tf32(acc[n], ah0, ah1, ah2, ah3, b0h, b1h);
            mma_tf32(acc[n], al0, al1, al2, al3, b0h, b1h);
            mma_tf32(acc[n], ah0, ah1, ah2, ah3, b0l, b1l);
        }
    }

    // ---- epilogue: bias + scatter ----
    // C layout: c0=(gidA, 2c), c1=(gidA, 2c+1), c2=(gidB, 2c), c3=(gidB, 2c+1)
#pragma unroll
    for (int n = 0; n < 8; n++) {
        int col0 = n * 8 + 2 * c;
        float bb0 = bx2[col0];
        float bb1 = bx2[col0 + 1];
        if (colA >= 0) {
            float* dst = outx + (size_t)colA * F_DIM + col0;
            atomicAdd(dst + 0, acc[n][0] + bb0);
            atomicAdd(dst + 1, acc[n][1] + bb1);
        }
        if (colB >= 0) {
            float* dst = outx + (size_t)colB * F_DIM + col0;
            atomicAdd(dst + 0, acc[n][2] + bb0);
            atomicAdd(dst + 1, acc[n][3] + bb1);
        }
    }
}

// ---------------------------------------------------------------------------
extern "C" void kernel_launch(void* const* d_in, const int* in_sizes, int n_in,
                              void* d_out, int out_size)
{
    const float* x   = (const float*)d_in[0];
    const float* pos = (const float*)d_in[1];
    const void*  ei  = d_in[2];
    const float* Wx1 = (const float*)d_in[3];
    const float* bx1 = (const float*)d_in[4];
    const float* Wx2 = (const float*)d_in[5];
    const float* bx2 = (const float*)d_in[6];
    const float* Wp1 = (const float*)d_in[7];
    const float* bp1 = (const float*)d_in[8];
    const float* Wp2 = (const float*)d_in[9];
    const float* bp2 = (const float*)d_in[10];

    int nNodes = in_sizes[0] / F_DIM;      // 100000
    int E      = in_sizes[2] / 2;          // 1000000

    float* outx   = (float*)d_out;                           // [N, 64]
    float* outpos = (float*)d_out + (size_t)nNodes * F_DIM;  // [N, 3]

    // Kernel 0: prep (fragment bake + index-width detect)
    int nCheck = (E < 32) ? E : 32;
    prep_kernel<<<1, 256>>>(Wx2, (const long long*)ei, nCheck, (long long)nNodes);

    // Kernel 1: node precompute + output zeroing
    size_t zeroCount = (size_t)nNodes * (F_DIM + 3);
    node_precompute<<<(nNodes + 7) / 8, 128>>>(x, Wx1, bx1, Wp1, bp1, Wp2, bp2,
                                               (float*)d_out, zeroCount, nNodes);

    // Kernel 2: edge kernel (tensor cores)
    edge_kernel<<<(E + 63) / 64, 128>>>(pos, ei, Wx1, bx2, outx, outpos, E, nNodes);
}

// round 5
// speedup vs baseline: 1.3606x; 1.0261x over previous
#include <cuda_runtime.h>
#include <cstdint>

// ---------------------------------------------------------------------------
// EquivariantMessagePassing — GB300 sm_103a — Round 5
//
//   h_e = silu( A[row] + B[col] + dist_sq * Wx1[128,:] )   (A has bx1 baked in)
//   msg_x_e = h_e @ Wx2 + bx2    -> red.global.add.v4.f32 scatter to out_x[col]
//   pos_upd = wpos[row]*rel_pos  -> atomic scatter to out_pos[col]
// Edge GEMM: mma.sync.m16n8k8.tf32, hi/lo 3-term split, k-permuted fragments.
// Epilogue: shfl.xor(1) pair-transpose -> 4-contiguous-col quads -> RED.128.
// ---------------------------------------------------------------------------

#define MAX_N 100000
#define F_DIM 64
#define H_DIM 128

__device__ float  g_A[(size_t)MAX_N * H_DIM];     // 51.2 MB
__device__ float  g_B[(size_t)MAX_N * H_DIM];     // 51.2 MB
__device__ float  g_wpos[MAX_N];
__device__ int    g_idx_is64;
__device__ float4 g_Wfrag[16 * 8 * 32];           // [t][n][lane] = (b0hi,b0lo,b1hi,b1lo)

__device__ __forceinline__ float silu_f(float v) {
    return __fdividef(v, 1.0f + __expf(-v));
}

__device__ __forceinline__ unsigned tf32_rnd(float v) {
    unsigned r;
    asm("cvt.rna.tf32.f32 %0, %1;" : "=r"(r) : "f"(v));
    return r;
}

__device__ __forceinline__ void mma_tf32(float acc[4],
                                         unsigned a0, unsigned a1, unsigned a2, unsigned a3,
                                         unsigned b0, unsigned b1) {
    asm volatile(
        "mma.sync.aligned.m16n8k8.row.col.f32.tf32.tf32.f32 "
        "{%0,%1,%2,%3}, {%4,%5,%6,%7}, {%8,%9}, {%0,%1,%2,%3};"
        : "+f"(acc[0]), "+f"(acc[1]), "+f"(acc[2]), "+f"(acc[3])
        : "r"(a0), "r"(a1), "r"(a2), "r"(a3), "r"(b0), "r"(b1));
}

__device__ __forceinline__ void load_edge(const void* ei, int e, int E, int is64,
                                          int nNodes, int& r, int& c)
{
    long long rv, cv;
    if (is64) {
        rv = ((const long long*)ei)[e];
        cv = ((const long long*)ei)[(size_t)E + e];
    } else {
        rv = ((const int*)ei)[e];
        cv = ((const int*)ei)[(size_t)E + e];
    }
    r = (rv >= 0 && rv < nNodes) ? (int)rv : -1;
    c = (cv >= 0 && cv < nNodes) ? (int)cv : -1;
    if (r < 0) c = -1;
}

// ---------------------------------------------------------------------------
// Kernel 1: per-node precompute + output zeroing + (block 0) prep:
//   - edge-index width detection
//   - W2 tf32 hi/lo fragment pre-bake:
//     g_Wfrag[(t*8+n)*32 + lane] = (hi(W2[k0][col]), lo, hi(W2[k1][col]), lo)
//       k0 = (lane%4)*32 + t, k1 = k0+16, col = n*8 + (lane>>2)
// ---------------------------------------------------------------------------
__global__ __launch_bounds__(128) void node_precompute(
    const float* __restrict__ x,
    const float* __restrict__ Wx1, const float* __restrict__ bx1,
    const float* __restrict__ Wx2,
    const float* __restrict__ Wp1, const float* __restrict__ bp1,
    const float* __restrict__ Wp2, const float* __restrict__ bp2,
    const long long* __restrict__ ei, int nCheck,
    float* __restrict__ out0, size_t zeroCount,
    int nNodes)
{
    const int NPB = 8;
    __shared__ float xs[NPB * F_DIM];
    __shared__ float wpart[4][NPB];

    int n0  = blockIdx.x * NPB;
    int tid = threadIdx.x;

    // ---- block 0: prep work ----
    if (blockIdx.x == 0) {
        if (tid == 0) {
            int is64 = 1;
            for (int i = 0; i < nCheck; i++) {
                long long v = ei[i];
                if (v < 0 || v >= (long long)nNodes) { is64 = 0; break; }
            }
            g_idx_is64 = is64;
        }
        for (int i = tid; i < 16 * 8 * 32; i += 128) {
            int lane = i & 31;
            int n    = (i >> 5) & 7;
            int t    = i >> 8;
            int c    = lane & 3;
            int gid  = lane >> 2;
            int col  = n * 8 + gid;
            int k0   = c * 32 + t;
            int k1   = k0 + 16;
            float w0 = Wx2[k0 * F_DIM + col];
            float w1 = Wx2[k1 * F_DIM + col];
            unsigned h0 = tf32_rnd(w0);
            unsigned h1 = tf32_rnd(w1);
            float l0 = w0 - __uint_as_float(h0);
            float l1 = w1 - __uint_as_float(h1);
            g_Wfrag[i] = make_float4(__uint_as_float(h0),
                                     __uint_as_float(tf32_rnd(l0)),
                                     __uint_as_float(h1),
                                     __uint_as_float(tf32_rnd(l1)));
        }
    }

    // ---- zero the output buffer (grid-stride) ----
    for (size_t i = (size_t)blockIdx.x * blockDim.x + tid; i < zeroCount;
         i += (size_t)gridDim.x * blockDim.x)
        out0[i] = 0.0f;

    // ---- stage x for 8 nodes ----
    for (int i = tid; i < NPB * F_DIM; i += 128) {
        int node = n0 + (i >> 6);
        xs[i] = (node < nNodes) ? x[(size_t)n0 * F_DIM + i] : 0.0f;
    }
    __syncthreads();

    float accA[NPB], accB[NPB], accP[NPB];
#pragma unroll
    for (int m = 0; m < NPB; m++) { accA[m] = 0.f; accB[m] = 0.f; accP[m] = 0.f; }

    const float* wx1a = Wx1 + tid;
    const float* wx1b = Wx1 + 64 * H_DIM + tid;
    const float* wp1c = Wp1 + tid;

#pragma unroll 4
    for (int k = 0; k < F_DIM; k++) {
        float w1 = wx1a[k * H_DIM];
        float w2 = wx1b[k * H_DIM];
        float wp = wp1c[k * H_DIM];
#pragma unroll
        for (int m = 0; m < NPB; m++) {
            float xv = xs[m * F_DIM + k];
            accA[m] = fmaf(xv, w1, accA[m]);
            accB[m] = fmaf(xv, w2, accB[m]);
            accP[m] = fmaf(xv, wp, accP[m]);
        }
    }

    float b1  = bx1[tid];
    float bp  = bp1[tid];
    float w2v = Wp2[tid];

#pragma unroll
    for (int m = 0; m < NPB; m++) {
        int node = n0 + m;
        if (node < nNodes) {
            g_A[(size_t)node * H_DIM + tid] = accA[m] + b1;
            g_B[(size_t)node * H_DIM + tid] = accB[m];
        }
        float hv = accP[m] + bp;
        float contrib = silu_f(hv) * w2v;
#pragma unroll
        for (int off = 16; off; off >>= 1)
            contrib += __shfl_xor_sync(0xffffffffu, contrib, off);
        if ((tid & 31) == 0) wpart[tid >> 5][m] = contrib;
    }
    __syncthreads();

    if (tid < NPB) {
        int node = n0 + tid;
        if (node < nNodes)
            g_wpos[node] = wpart[0][tid] + wpart[1][tid] + wpart[2][tid] + wpart[3][tid] + bp2[0];
    }
}

// ---------------------------------------------------------------------------
// Kernel 2: edge kernel (tensor cores). 128 threads (4 warps), 64 edges/block.
// ---------------------------------------------------------------------------
__global__ __launch_bounds__(128) void edge_kernel(
    const float* __restrict__ pos,
    const void*  __restrict__ ei,
    const float* __restrict__ Wx1,      // row 128 = dist_sq weights
    const float* __restrict__ bx2,
    float* __restrict__ outx,           // [N, 64]
    float* __restrict__ outpos,         // [N, 3]
    int E, int nNodes)
{
    const unsigned FULL = 0xffffffffu;
    int tid   = threadIdx.x;
    int lane  = tid & 31;
    int warp  = tid >> 5;
    int warpE = blockIdx.x * 64 + warp * 16;
    int is64  = g_idx_is64;

    // ---- lanes 0..15: per-edge index load, dist, pos-branch scatter ----
    int   rIdx = -1, cIdx = -1;
    float dsq  = 0.f;
    if (lane < 16) {
        int gE = warpE + lane;
        if (gE < E) load_edge(ei, gE, E, is64, nNodes, rIdx, cIdx);
        if (cIdx >= 0) {
            float dx = pos[rIdx * 3 + 0] - pos[cIdx * 3 + 0];
            float dy = pos[rIdx * 3 + 1] - pos[cIdx * 3 + 1];
            float dz = pos[rIdx * 3 + 2] - pos[cIdx * 3 + 2];
            dsq = dx * dx + dy * dy + dz * dz;
            float wp = g_wpos[rIdx];
            atomicAdd(&outpos[(size_t)cIdx * 3 + 0], wp * dx);
            atomicAdd(&outpos[(size_t)cIdx * 3 + 1], wp * dy);
            atomicAdd(&outpos[(size_t)cIdx * 3 + 2], wp * dz);
        }
    }

    int gidA = lane >> 2;          // edge (m-row) 0..7
    int gidB = gidA + 8;           // edge (m-row) 8..15
    int c    = lane & 3;           // thread-in-group

    int   rowA = __shfl_sync(FULL, rIdx, gidA);
    int   colA = __shfl_sync(FULL, cIdx, gidA);
    float dsqA = __shfl_sync(FULL, dsq,  gidA);
    int   rowB = __shfl_sync(FULL, rIdx, gidB);
    int   colB = __shfl_sync(FULL, cIdx, gidB);
    float dsqB = __shfl_sync(FULL, dsq,  gidB);

    // ---- gather + activation into registers (k = c*32 + 0..31) ----
    float hA[32], hB[32];
    const float* w128 = Wx1 + H_DIM * H_DIM;   // row 128 of [129,128]

#pragma unroll
    for (int j = 0; j < 8; j++) {
        int k = c * 32 + 4 * j;
        float4 w4 = *(const float4*)(w128 + k);
        if (colA >= 0) {
            float4 a4 = *(const float4*)(g_A + (size_t)rowA * H_DIM + k);
            float4 b4 = *(const float4*)(g_B + (size_t)colA * H_DIM + k);
            hA[4 * j + 0] = silu_f(a4.x + b4.x + dsqA * w4.x);
            hA[4 * j + 1] = silu_f(a4.y + b4.y + dsqA * w4.y);
            hA[4 * j + 2] = silu_f(a4.z + b4.z + dsqA * w4.z);
            hA[4 * j + 3] = silu_f(a4.w + b4.w + dsqA * w4.w);
        } else {
            hA[4 * j + 0] = 0.f; hA[4 * j + 1] = 0.f;
            hA[4 * j + 2] = 0.f; hA[4 * j + 3] = 0.f;
        }
        if (colB >= 0) {
            float4 a4 = *(const float4*)(g_A + (size_t)rowB * H_DIM + k);
            float4 b4 = *(const float4*)(g_B + (size_t)colB * H_DIM + k);
            hB[4 * j + 0] = silu_f(a4.x + b4.x + dsqB * w4.x);
            hB[4 * j + 1] = silu_f(a4.y + b4.y + dsqB * w4.y);
            hB[4 * j + 2] = silu_f(a4.z + b4.z + dsqB * w4.z);
            hB[4 * j + 3] = silu_f(a4.w + b4.w + dsqB * w4.w);
        } else {
            hB[4 * j + 0] = 0.f; hB[4 * j + 1] = 0.f;
            hB[4 * j + 2] = 0.f; hB[4 * j + 3] = 0.f;
        }
    }

    // ---- tensor-core GEMM: D[16 edges][64 cols] ----
    float acc[8][4];
#pragma unroll
    for (int n = 0; n < 8; n++)
#pragma unroll
        for (int q = 0; q < 4; q++) acc[n][q] = 0.f;

    const float4* wf = g_Wfrag;

#pragma unroll
    for (int t = 0; t < 16; t++) {
        float a0 = hA[t],      a1 = hB[t];
        float a2 = hA[16 + t], a3 = hB[16 + t];
        unsigned ah0 = tf32_rnd(a0), ah1 = tf32_rnd(a1);
        unsigned ah2 = tf32_rnd(a2), ah3 = tf32_rnd(a3);
        unsigned al0 = tf32_rnd(a0 - __uint_as_float(ah0));
        unsigned al1 = tf32_rnd(a1 - __uint_as_float(ah1));
        unsigned al2 = tf32_rnd(a2 - __uint_as_float(ah2));
        unsigned al3 = tf32_rnd(a3 - __uint_as_float(ah3));
#pragma unroll
        for (int n = 0; n < 8; n++) {
            float4 b = wf[(t * 8 + n) * 32 + lane];
            unsigned b0h = __float_as_uint(b.x), b0l = __float_as_uint(b.y);
            unsigned b1h = __float_as_uint(b.z), b1l = __float_as_uint(b.w);
            mma_tf32(acc[n], ah0, ah1, ah2, ah3, b0h, b1h);
            mma_tf32(acc[n], al0, al1, al2, al3, b0h, b1h);
            mma_tf32(acc[n], ah0, ah1, ah2, ah3, b0l, b1l);
        }
    }

    // ---- epilogue: pair-transpose via shfl.xor(1), bias, RED.128 scatter ----
    // C layout: c0,c1 = (edge gidA, cols 2c,2c+1); c2,c3 = (edge gidB, same cols).
    // Lane pair (c even, c odd): even lane keeps edgeA quad cols 2c..2c+3,
    // odd lane keeps edgeB quad cols 2(c-1)..2(c-1)+3.
    bool evenc = ((c & 1) == 0);
    int  myNode = evenc ? colA : colB;
    int  colBase0 = evenc ? (2 * c) : (2 * c - 2);
#pragma unroll
    for (int n = 0; n < 8; n++) {
        float o0 = __shfl_xor_sync(FULL, acc[n][0], 1);
        float o1 = __shfl_xor_sync(FULL, acc[n][1], 1);
        float o2 = __shfl_xor_sync(FULL, acc[n][2], 1);
        float o3 = __shfl_xor_sync(FULL, acc[n][3], 1);
        float4 q;
        if (evenc) q = make_float4(acc[n][0], acc[n][1], o0, o1);
        else       q = make_float4(o2, o3, acc[n][2], acc[n][3]);
        if (myNode >= 0) {
            int colb = n * 8 + colBase0;
            float4 bb = *(const float4*)(bx2 + colb);
            float* dst = outx + (size_t)myNode * F_DIM + colb;
            asm volatile("red.global.add.v4.f32 [%0], {%1,%2,%3,%4};"
                         :: "l"(dst),
                            "f"(q.x + bb.x), "f"(q.y + bb.y),
                            "f"(q.z + bb.z), "f"(q.w + bb.w)
                         : "memory");
        }
    }
}

// ---------------------------------------------------------------------------
extern "C" void kernel_launch(void* const* d_in, const int* in_sizes, int n_in,
                              void* d_out, int out_size)
{
    const float* x   = (const float*)d_in[0];
    const float* pos = (const float*)d_in[1];
    const void*  ei  = d_in[2];
    const float* Wx1 = (const float*)d_in[3];
    const float* bx1 = (const float*)d_in[4];
    const float* Wx2 = (const float*)d_in[5];
    const float* bx2 = (const float*)d_in[6];
    const float* Wp1 = (const float*)d_in[7];
    const float* bp1 = (const float*)d_in[8];
    const float* Wp2 = (const float*)d_in[9];
    const float* bp2 = (const float*)d_in[10];

    int nNodes = in_sizes[0] / F_DIM;      // 100000
    int E      = in_sizes[2] / 2;          // 1000000

    float* outx   = (float*)d_out;                           // [N, 64]
    float* outpos = (float*)d_out + (size_t)nNodes * F_DIM;  // [N, 3]

    int nCheck = (E < 32) ? E : 32;
    size_t zeroCount = (size_t)nNodes * (F_DIM + 3);

    // Kernel 1: node precompute + zeroing + prep (block 0)
    node_precompute<<<(nNodes + 7) / 8, 128>>>(
        x, Wx1, bx1, Wx2, Wp1, bp1, Wp2, bp2,
        (const long long*)ei, nCheck,
        (float*)d_out, zeroCount, nNodes);

    // Kernel 2: edge kernel (tensor cores)
    edge_kernel<<<(E + 63) / 64, 128>>>(pos, ei, Wx1, bx2, outx, outpos, E, nNodes);
}

// round 6
// speedup vs baseline: 1.5841x; 1.1643x over previous
#include <cuda_runtime.h>
#include <cstdint>

// ---------------------------------------------------------------------------
// EquivariantMessagePassing — GB300 sm_103a — Round 6
//
//   h_e = silu( A[row] + B[col] + dist_sq * Wx1[128,:] )   (A has bx1 baked in)
//   msg_x_e = h_e @ Wx2 + bx2    -> red.global.add.v4.f32 scatter to out_x[col]
//   pos_upd = wpos[row]*rel_pos  -> atomic scatter to out_pos[col]
// Edge GEMM: mma.sync.m16n8k8.tf32, hi/lo 3-term split, k-permuted fragments.
// R6: Wfrag staged in 64KB smem (kills L1 LDG storm), fused gather+mma loop
// (16 live h regs instead of 64), 256 thr / 2 blocks/SM.
// ---------------------------------------------------------------------------

#define MAX_N 100000
#define F_DIM 64
#define H_DIM 128

__device__ float  g_A[(size_t)MAX_N * H_DIM];     // 51.2 MB
__device__ float  g_B[(size_t)MAX_N * H_DIM];     // 51.2 MB
__device__ float  g_wpos[MAX_N];
__device__ int    g_idx_is64;
__device__ float4 g_Wfrag[16 * 8 * 32];           // [t][n][lane] = (b0hi,b0lo,b1hi,b1lo)

__device__ __forceinline__ float silu_f(float v) {
    return __fdividef(v, 1.0f + __expf(-v));
}

__device__ __forceinline__ unsigned tf32_rnd(float v) {
    unsigned r;
    asm("cvt.rna.tf32.f32 %0, %1;" : "=r"(r) : "f"(v));
    return r;
}

__device__ __forceinline__ void mma_tf32(float acc[4],
                                         unsigned a0, unsigned a1, unsigned a2, unsigned a3,
                                         unsigned b0, unsigned b1) {
    asm volatile(
        "mma.sync.aligned.m16n8k8.row.col.f32.tf32.tf32.f32 "
        "{%0,%1,%2,%3}, {%4,%5,%6,%7}, {%8,%9}, {%0,%1,%2,%3};"
        : "+f"(acc[0]), "+f"(acc[1]), "+f"(acc[2]), "+f"(acc[3])
        : "r"(a0), "r"(a1), "r"(a2), "r"(a3), "r"(b0), "r"(b1));
}

__device__ __forceinline__ void load_edge(const void* ei, int e, int E, int is64,
                                          int nNodes, int& r, int& c)
{
    long long rv, cv;
    if (is64) {
        rv = ((const long long*)ei)[e];
        cv = ((const long long*)ei)[(size_t)E + e];
    } else {
        rv = ((const int*)ei)[e];
        cv = ((const int*)ei)[(size_t)E + e];
    }
    r = (rv >= 0 && rv < nNodes) ? (int)rv : -1;
    c = (cv >= 0 && cv < nNodes) ? (int)cv : -1;
    if (r < 0) c = -1;
}

// ---------------------------------------------------------------------------
// Kernel 1: per-node precompute + output zeroing + (block 0) prep
// ---------------------------------------------------------------------------
__global__ __launch_bounds__(128) void node_precompute(
    const float* __restrict__ x,
    const float* __restrict__ Wx1, const float* __restrict__ bx1,
    const float* __restrict__ Wx2,
    const float* __restrict__ Wp1, const float* __restrict__ bp1,
    const float* __restrict__ Wp2, const float* __restrict__ bp2,
    const long long* __restrict__ ei, int nCheck,
    float* __restrict__ out0, size_t zeroCount,
    int nNodes)
{
    const int NPB = 8;
    __shared__ float xs[NPB * F_DIM];
    __shared__ float wpart[4][NPB];

    int n0  = blockIdx.x * NPB;
    int tid = threadIdx.x;

    // ---- block 0: prep (idx width detect + Wfrag bake) ----
    if (blockIdx.x == 0) {
        if (tid == 0) {
            int is64 = 1;
            for (int i = 0; i < nCheck; i++) {
                long long v = ei[i];
                if (v < 0 || v >= (long long)nNodes) { is64 = 0; break; }
            }
            g_idx_is64 = is64;
        }
        for (int i = tid; i < 16 * 8 * 32; i += 128) {
            int lane = i & 31;
            int n    = (i >> 5) & 7;
            int t    = i >> 8;
            int c    = lane & 3;
            int gid  = lane >> 2;
            int col  = n * 8 + gid;
            int k0   = c * 32 + t;
            int k1   = k0 + 16;
            float w0 = Wx2[k0 * F_DIM + col];
            float w1 = Wx2[k1 * F_DIM + col];
            unsigned h0 = tf32_rnd(w0);
            unsigned h1 = tf32_rnd(w1);
            float l0 = w0 - __uint_as_float(h0);
            float l1 = w1 - __uint_as_float(h1);
            g_Wfrag[i] = make_float4(__uint_as_float(h0),
                                     __uint_as_float(tf32_rnd(l0)),
                                     __uint_as_float(h1),
                                     __uint_as_float(tf32_rnd(l1)));
        }
    }

    // ---- zero the output buffer (grid-stride) ----
    for (size_t i = (size_t)blockIdx.x * blockDim.x + tid; i < zeroCount;
         i += (size_t)gridDim.x * blockDim.x)
        out0[i] = 0.0f;

    // ---- stage x for 8 nodes ----
    for (int i = tid; i < NPB * F_DIM; i += 128) {
        int node = n0 + (i >> 6);
        xs[i] = (node < nNodes) ? x[(size_t)n0 * F_DIM + i] : 0.0f;
    }
    __syncthreads();

    float accA[NPB], accB[NPB], accP[NPB];
#pragma unroll
    for (int m = 0; m < NPB; m++) { accA[m] = 0.f; accB[m] = 0.f; accP[m] = 0.f; }

    const float* wx1a = Wx1 + tid;
    const float* wx1b = Wx1 + 64 * H_DIM + tid;
    const float* wp1c = Wp1 + tid;

#pragma unroll 4
    for (int k = 0; k < F_DIM; k++) {
        float w1 = wx1a[k * H_DIM];
        float w2 = wx1b[k * H_DIM];
        float wp = wp1c[k * H_DIM];
#pragma unroll
        for (int m = 0; m < NPB; m++) {
            float xv = xs[m * F_DIM + k];
            accA[m] = fmaf(xv, w1, accA[m]);
            accB[m] = fmaf(xv, w2, accB[m]);
            accP[m] = fmaf(xv, wp, accP[m]);
        }
    }

    float b1  = bx1[tid];
    float bp  = bp1[tid];
    float w2v = Wp2[tid];

#pragma unroll
    for (int m = 0; m < NPB; m++) {
        int node = n0 + m;
        if (node < nNodes) {
            g_A[(size_t)node * H_DIM + tid] = accA[m] + b1;
            g_B[(size_t)node * H_DIM + tid] = accB[m];
        }
        float hv = accP[m] + bp;
        float contrib = silu_f(hv) * w2v;
#pragma unroll
        for (int off = 16; off; off >>= 1)
            contrib += __shfl_xor_sync(0xffffffffu, contrib, off);
        if ((tid & 31) == 0) wpart[tid >> 5][m] = contrib;
    }
    __syncthreads();

    if (tid < NPB) {
        int node = n0 + tid;
        if (node < nNodes)
            g_wpos[node] = wpart[0][tid] + wpart[1][tid] + wpart[2][tid] + wpart[3][tid] + bp2[0];
    }
}

// ---------------------------------------------------------------------------
// Kernel 2: edge kernel (tensor cores). 256 threads (8 warps), 128 edges/block.
// Wfrag in smem; fused gather+mma loop keeps only 16 h values live.
// ---------------------------------------------------------------------------
__global__ __launch_bounds__(256, 2) void edge_kernel(
    const float* __restrict__ pos,
    const void*  __restrict__ ei,
    const float* __restrict__ Wx1,      // row 128 = dist_sq weights
    const float* __restrict__ bx2,
    float* __restrict__ outx,           // [N, 64]
    float* __restrict__ outpos,         // [N, 3]
    int E, int nNodes)
{
    extern __shared__ float4 sWf[];     // 16*8*32 float4 = 64KB

    const unsigned FULL = 0xffffffffu;
    int tid   = threadIdx.x;
    int lane  = tid & 31;
    int warp  = tid >> 5;
    int warpE = blockIdx.x * 128 + warp * 16;
    int is64  = g_idx_is64;

    // ---- cooperative Wfrag stage (4096 float4 over 256 threads) ----
#pragma unroll
    for (int i = 0; i < 16; i++)
        sWf[i * 256 + tid] = g_Wfrag[i * 256 + tid];

    // ---- lanes 0..15: per-edge index load, dist, pos-branch scatter ----
    int   rIdx = -1, cIdx = -1;
    float dsq  = 0.f;
    if (lane < 16) {
        int gE = warpE + lane;
        if (gE < E) load_edge(ei, gE, E, is64, nNodes, rIdx, cIdx);
        if (cIdx >= 0) {
            float dx = pos[rIdx * 3 + 0] - pos[cIdx * 3 + 0];
            float dy = pos[rIdx * 3 + 1] - pos[cIdx * 3 + 1];
            float dz = pos[rIdx * 3 + 2] - pos[cIdx * 3 + 2];
            dsq = dx * dx + dy * dy + dz * dz;
            float wp = g_wpos[rIdx];
            atomicAdd(&outpos[(size_t)cIdx * 3 + 0], wp * dx);
            atomicAdd(&outpos[(size_t)cIdx * 3 + 1], wp * dy);
            atomicAdd(&outpos[(size_t)cIdx * 3 + 2], wp * dz);
        }
    }

    int gidA = lane >> 2;          // edge (m-row) 0..7
    int gidB = gidA + 8;           // edge (m-row) 8..15
    int c    = lane & 3;           // thread-in-group

    int   rowA = __shfl_sync(FULL, rIdx, gidA);
    int   colA = __shfl_sync(FULL, cIdx, gidA);
    float dsqA = __shfl_sync(FULL, dsq,  gidA);
    int   rowB = __shfl_sync(FULL, rIdx, gidB);
    int   colB = __shfl_sync(FULL, cIdx, gidB);
    float dsqB = __shfl_sync(FULL, dsq,  gidB);

    const float* w128 = Wx1 + H_DIM * H_DIM;   // row 128 of [129,128]
    const float* pAr  = (colA >= 0) ? g_A + (size_t)rowA * H_DIM : g_A;
    const float* pAc  = (colA >= 0) ? g_B + (size_t)colA * H_DIM : g_B;
    const float* pBr  = (colB >= 0) ? g_A + (size_t)rowB * H_DIM : g_A;
    const float* pBc  = (colB >= 0) ? g_B + (size_t)colB * H_DIM : g_B;
    bool okA = (colA >= 0), okB = (colB >= 0);

    float acc[8][4];
#pragma unroll
    for (int n = 0; n < 8; n++)
#pragma unroll
        for (int q = 0; q < 4; q++) acc[n][q] = 0.f;

    __syncthreads();   // sWf ready

    // ---- fused gather + mma: j covers k-chunks [c*32+4j] and [c*32+16+4j] ----
#pragma unroll
    for (int j = 0; j < 4; j++) {
        int k0 = c * 32 + 4 * j;
        int k1 = k0 + 16;
        float4 w40 = *(const float4*)(w128 + k0);
        float4 w41 = *(const float4*)(w128 + k1);

        float hA0[4], hA1[4], hB0[4], hB1[4];
        if (okA) {
            float4 a0 = *(const float4*)(pAr + k0);
            float4 b0 = *(const float4*)(pAc + k0);
            float4 a1 = *(const float4*)(pAr + k1);
            float4 b1 = *(const float4*)(pAc + k1);
            hA0[0] = silu_f(a0.x + b0.x + dsqA * w40.x);
            hA0[1] = silu_f(a0.y + b0.y + dsqA * w40.y);
            hA0[2] = silu_f(a0.z + b0.z + dsqA * w40.z);
            hA0[3] = silu_f(a0.w + b0.w + dsqA * w40.w);
            hA1[0] = silu_f(a1.x + b1.x + dsqA * w41.x);
            hA1[1] = silu_f(a1.y + b1.y + dsqA * w41.y);
            hA1[2] = silu_f(a1.z + b1.z + dsqA * w41.z);
            hA1[3] = silu_f(a1.w + b1.w + dsqA * w41.w);
        } else {
#pragma unroll
            for (int q = 0; q < 4; q++) { hA0[q] = 0.f; hA1[q] = 0.f; }
        }
        if (okB) {
            float4 a0 = *(const float4*)(pBr + k0);
            float4 b0 = *(const float4*)(pBc + k0);
            float4 a1 = *(const float4*)(pBr + k1);
            float4 b1 = *(const float4*)(pBc + k1);
            hB0[0] = silu_f(a0.x + b0.x + dsqB * w40.x);
            hB0[1] = silu_f(a0.y + b0.y + dsqB * w40.y);
            hB0[2] = silu_f(a0.z + b0.z + dsqB * w40.z);
            hB0[3] = silu_f(a0.w + b0.w + dsqB * w40.w);
            hB1[0] = silu_f(a1.x + b1.x + dsqB * w41.x);
            hB1[1] = silu_f(a1.y + b1.y + dsqB * w41.y);
            hB1[2] = silu_f(a1.z + b1.z + dsqB * w41.z);
            hB1[3] = silu_f(a1.w + b1.w + dsqB * w41.w);
        } else {
#pragma unroll
            for (int q = 0; q < 4; q++) { hB0[q] = 0.f; hB1[q] = 0.f; }
        }

#pragma unroll
        for (int tt = 0; tt < 4; tt++) {
            int t = 4 * j + tt;
            float a0 = hA0[tt], a1 = hB0[tt];
            float a2 = hA1[tt], a3 = hB1[tt];
            unsigned ah0 = tf32_rnd(a0), ah1 = tf32_rnd(a1);
            unsigned ah2 = tf32_rnd(a2), ah3 = tf32_rnd(a3);
            unsigned al0 = tf32_rnd(a0 - __uint_as_float(ah0));
            unsigned al1 = tf32_rnd(a1 - __uint_as_float(ah1));
            unsigned al2 = tf32_rnd(a2 - __uint_as_float(ah2));
            unsigned al3 = tf32_rnd(a3 - __uint_as_float(ah3));
            const float4* wrow = sWf + (size_t)t * 8 * 32 + lane;
#pragma unroll
            for (int n = 0; n < 8; n++) {
                float4 b = wrow[n * 32];
                unsigned b0h = __float_as_uint(b.x), b0l = __float_as_uint(b.y);
                unsigned b1h = __float_as_uint(b.z), b1l = __float_as_uint(b.w);
                mma_tf32(acc[n], ah0, ah1, ah2, ah3, b0h, b1h);
                mma_tf32(acc[n], al0, al1, al2, al3, b0h, b1h);
                mma_tf32(acc[n], ah0, ah1, ah2, ah3, b0l, b1l);
            }
        }
    }

    // ---- epilogue: pair-transpose via shfl.xor(1), bias, RED.128 scatter ----
    bool evenc = ((c & 1) == 0);
    int  myNode = evenc ? colA : colB;
    int  colBase0 = evenc ? (2 * c) : (2 * c - 2);
#pragma unroll
    for (int n = 0; n < 8; n++) {
        float o0 = __shfl_xor_sync(FULL, acc[n][0], 1);
        float o1 = __shfl_xor_sync(FULL, acc[n][1], 1);
        float o2 = __shfl_xor_sync(FULL, acc[n][2], 1);
        float o3 = __shfl_xor_sync(FULL, acc[n][3], 1);
        float4 q;
        if (evenc) q = make_float4(acc[n][0], acc[n][1], o0, o1);
        else       q = make_float4(o2, o3, acc[n][2], acc[n][3]);
        if (myNode >= 0) {
            int colb = n * 8 + colBase0;
            float4 bb = *(const float4*)(bx2 + colb);
            float* dst = outx + (size_t)myNode * F_DIM + colb;
            asm volatile("red.global.add.v4.f32 [%0], {%1,%2,%3,%4};"
                         :: "l"(dst),
                            "f"(q.x + bb.x), "f"(q.y + bb.y),
                            "f"(q.z + bb.z), "f"(q.w + bb.w)
                         : "memory");
        }
    }
}

// ---------------------------------------------------------------------------
extern "C" void kernel_launch(void* const* d_in, const int* in_sizes, int n_in,
                              void* d_out, int out_size)
{
    const float* x   = (const float*)d_in[0];
    const float* pos = (const float*)d_in[1];
    const void*  ei  = d_in[2];
    const float* Wx1 = (const float*)d_in[3];
    const float* bx1 = (const float*)d_in[4];
    const float* Wx2 = (const float*)d_in[5];
    const float* bx2 = (const float*)d_in[6];
    const float* Wp1 = (const float*)d_in[7];
    const float* bp1 = (const float*)d_in[8];
    const float* Wp2 = (const float*)d_in[9];
    const float* bp2 = (const float*)d_in[10];

    int nNodes = in_sizes[0] / F_DIM;      // 100000
    int E      = in_sizes[2] / 2;          // 1000000

    float* outx   = (float*)d_out;                           // [N, 64]
    float* outpos = (float*)d_out + (size_t)nNodes * F_DIM;  // [N, 3]

    int nCheck = (E < 32) ? E : 32;
    size_t zeroCount = (size_t)nNodes * (F_DIM + 3);

    // Kernel 1: node precompute + zeroing + prep (block 0)
    node_precompute<<<(nNodes + 7) / 8, 128>>>(
        x, Wx1, bx1, Wx2, Wp1, bp1, Wp2, bp2,
        (const long long*)ei, nCheck,
        (float*)d_out, zeroCount, nNodes);

    // Kernel 2: edge kernel (tensor cores, smem-staged Wfrag)
    size_t shmem = sizeof(float4) * 16 * 8 * 32;   // 64 KB
    cudaFuncSetAttribute(edge_kernel, cudaFuncAttributeMaxDynamicSharedMemorySize, (int)shmem);
    edge_kernel<<<(E + 127) / 128, 256, shmem>>>(pos, ei, Wx1, bx2, outx, outpos, E, nNodes);
}

// round 7
// speedup vs baseline: 1.6190x; 1.0220x over previous
#include <cuda_runtime.h>
#include <cstdint>

// ---------------------------------------------------------------------------
// EquivariantMessagePassing — GB300 sm_103a — Round 7
//
//   h_e = silu( A[row] + B[col] + dist_sq * Wx1[128,:] )   (A has bx1 baked in)
//   msg_x_e = h_e @ Wx2 + bx2    -> red.global.add.v4.f32 scatter to out_x[col]
//   pos_upd = wpos[row]*rel_pos  -> atomic scatter to out_pos[col]
// Edge GEMM: mma.sync.m16n8k8.tf32, hi/lo 3-term split, k-permuted fragments.
// R7: 32 edges/warp (two m16 tiles share every smem B-fragment read ->
// Wfrag LDS traffic halved), 128 thr/block, 3 blocks/SM.
// ---------------------------------------------------------------------------

#define MAX_N 100000
#define F_DIM 64
#define H_DIM 128

__device__ float  g_A[(size_t)MAX_N * H_DIM];     // 51.2 MB
__device__ float  g_B[(size_t)MAX_N * H_DIM];     // 51.2 MB
__device__ float  g_wpos[MAX_N];
__device__ int    g_idx_is64;
__device__ float4 g_Wfrag[16 * 8 * 32];           // [t][n][lane] = (b0hi,b0lo,b1hi,b1lo)

__device__ __forceinline__ float silu_f(float v) {
    return __fdividef(v, 1.0f + __expf(-v));
}

__device__ __forceinline__ unsigned tf32_rnd(float v) {
    unsigned r;
    asm("cvt.rna.tf32.f32 %0, %1;" : "=r"(r) : "f"(v));
    return r;
}

__device__ __forceinline__ void mma_tf32(float acc[4],
                                         unsigned a0, unsigned a1, unsigned a2, unsigned a3,
                                         unsigned b0, unsigned b1) {
    asm volatile(
        "mma.sync.aligned.m16n8k8.row.col.f32.tf32.tf32.f32 "
        "{%0,%1,%2,%3}, {%4,%5,%6,%7}, {%8,%9}, {%0,%1,%2,%3};"
        : "+f"(acc[0]), "+f"(acc[1]), "+f"(acc[2]), "+f"(acc[3])
        : "r"(a0), "r"(a1), "r"(a2), "r"(a3), "r"(b0), "r"(b1));
}

__device__ __forceinline__ void load_edge(const void* ei, int e, int E, int is64,
                                          int nNodes, int& r, int& c)
{
    long long rv, cv;
    if (is64) {
        rv = ((const long long*)ei)[e];
        cv = ((const long long*)ei)[(size_t)E + e];
    } else {
        rv = ((const int*)ei)[e];
        cv = ((const int*)ei)[(size_t)E + e];
    }
    r = (rv >= 0 && rv < nNodes) ? (int)rv : -1;
    c = (cv >= 0 && cv < nNodes) ? (int)cv : -1;
    if (r < 0) c = -1;
}

// gather + silu for one edge, two k-chunks (k0, k1), 4 values each
__device__ __forceinline__ void gather_h(const float* pr, const float* pc,
                                         float dsq, bool ok,
                                         const float4& w40, const float4& w41,
                                         int k0, int k1,
                                         float h0[4], float h1[4])
{
    if (ok) {
        float4 a0 = *(const float4*)(pr + k0);
        float4 b0 = *(const float4*)(pc + k0);
        float4 a1 = *(const float4*)(pr + k1);
        float4 b1 = *(const float4*)(pc + k1);
        h0[0] = silu_f(a0.x + b0.x + dsq * w40.x);
        h0[1] = silu_f(a0.y + b0.y + dsq * w40.y);
        h0[2] = silu_f(a0.z + b0.z + dsq * w40.z);
        h0[3] = silu_f(a0.w + b0.w + dsq * w40.w);
        h1[0] = silu_f(a1.x + b1.x + dsq * w41.x);
        h1[1] = silu_f(a1.y + b1.y + dsq * w41.y);
        h1[2] = silu_f(a1.z + b1.z + dsq * w41.z);
        h1[3] = silu_f(a1.w + b1.w + dsq * w41.w);
    } else {
#pragma unroll
        for (int q = 0; q < 4; q++) { h0[q] = 0.f; h1[q] = 0.f; }
    }
}

// ---------------------------------------------------------------------------
// Kernel 1: per-node precompute + output zeroing + (block 0) prep
// ---------------------------------------------------------------------------
__global__ __launch_bounds__(128) void node_precompute(
    const float* __restrict__ x,
    const float* __restrict__ Wx1, const float* __restrict__ bx1,
    const float* __restrict__ Wx2,
    const float* __restrict__ Wp1, const float* __restrict__ bp1,
    const float* __restrict__ Wp2, const float* __restrict__ bp2,
    const long long* __restrict__ ei, int nCheck,
    float* __restrict__ out0, size_t zeroCount,
    int nNodes)
{
    const int NPB = 8;
    __shared__ float xs[NPB * F_DIM];
    __shared__ float wpart[4][NPB];

    int n0  = blockIdx.x * NPB;
    int tid = threadIdx.x;

    if (blockIdx.x == 0) {
        if (tid == 0) {
            int is64 = 1;
            for (int i = 0; i < nCheck; i++) {
                long long v = ei[i];
                if (v < 0 || v >= (long long)nNodes) { is64 = 0; break; }
            }
            g_idx_is64 = is64;
        }
        for (int i = tid; i < 16 * 8 * 32; i += 128) {
            int lane = i & 31;
            int n    = (i >> 5) & 7;
            int t    = i >> 8;
            int c    = lane & 3;
            int gid  = lane >> 2;
            int col  = n * 8 + gid;
            int k0   = c * 32 + t;
            int k1   = k0 + 16;
            float w0 = Wx2[k0 * F_DIM + col];
            float w1 = Wx2[k1 * F_DIM + col];
            unsigned h0 = tf32_rnd(w0);
            unsigned h1 = tf32_rnd(w1);
            float l0 = w0 - __uint_as_float(h0);
            float l1 = w1 - __uint_as_float(h1);
            g_Wfrag[i] = make_float4(__uint_as_float(h0),
                                     __uint_as_float(tf32_rnd(l0)),
                                     __uint_as_float(h1),
                                     __uint_as_float(tf32_rnd(l1)));
        }
    }

    for (size_t i = (size_t)blockIdx.x * blockDim.x + tid; i < zeroCount;
         i += (size_t)gridDim.x * blockDim.x)
        out0[i] = 0.0f;

    for (int i = tid; i < NPB * F_DIM; i += 128) {
        int node = n0 + (i >> 6);
        xs[i] = (node < nNodes) ? x[(size_t)n0 * F_DIM + i] : 0.0f;
    }
    __syncthreads();

    float accA[NPB], accB[NPB], accP[NPB];
#pragma unroll
    for (int m = 0; m < NPB; m++) { accA[m] = 0.f; accB[m] = 0.f; accP[m] = 0.f; }

    const float* wx1a = Wx1 + tid;
    const float* wx1b = Wx1 + 64 * H_DIM + tid;
    const float* wp1c = Wp1 + tid;

#pragma unroll 4
    for (int k = 0; k < F_DIM; k++) {
        float w1 = wx1a[k * H_DIM];
        float w2 = wx1b[k * H_DIM];
        float wp = wp1c[k * H_DIM];
#pragma unroll
        for (int m = 0; m < NPB; m++) {
            float xv = xs[m * F_DIM + k];
            accA[m] = fmaf(xv, w1, accA[m]);
            accB[m] = fmaf(xv, w2, accB[m]);
            accP[m] = fmaf(xv, wp, accP[m]);
        }
    }

    float b1  = bx1[tid];
    float bp  = bp1[tid];
    float w2v = Wp2[tid];

#pragma unroll
    for (int m = 0; m < NPB; m++) {
        int node = n0 + m;
        if (node < nNodes) {
            g_A[(size_t)node * H_DIM + tid] = accA[m] + b1;
            g_B[(size_t)node * H_DIM + tid] = accB[m];
        }
        float hv = accP[m] + bp;
        float contrib = silu_f(hv) * w2v;
#pragma unroll
        for (int off = 16; off; off >>= 1)
            contrib += __shfl_xor_sync(0xffffffffu, contrib, off);
        if ((tid & 31) == 0) wpart[tid >> 5][m] = contrib;
    }
    __syncthreads();

    if (tid < NPB) {
        int node = n0 + tid;
        if (node < nNodes)
            g_wpos[node] = wpart[0][tid] + wpart[1][tid] + wpart[2][tid] + wpart[3][tid] + bp2[0];
    }
}

// ---------------------------------------------------------------------------
// Kernel 2: edge kernel. 128 threads (4 warps), 32 edges/warp (two m16 tiles),
// 128 edges/block. Wfrag in smem, each B-fragment read feeds both tiles.
// ---------------------------------------------------------------------------
__global__ __launch_bounds__(128, 3) void edge_kernel(
    const float* __restrict__ pos,
    const void*  __restrict__ ei,
    const float* __restrict__ Wx1,      // row 128 = dist_sq weights
    const float* __restrict__ bx2,
    float* __restrict__ outx,           // [N, 64]
    float* __restrict__ outpos,         // [N, 3]
    int E, int nNodes)
{
    extern __shared__ float4 sWf[];     // 16*8*32 float4 = 64KB

    const unsigned FULL = 0xffffffffu;
    int tid   = threadIdx.x;
    int lane  = tid & 31;
    int warp  = tid >> 5;
    int warpE = blockIdx.x * 128 + warp * 32;
    int is64  = g_idx_is64;

    // ---- cooperative Wfrag stage (4096 float4 over 128 threads) ----
#pragma unroll
    for (int i = 0; i < 32; i++)
        sWf[i * 128 + tid] = g_Wfrag[i * 128 + tid];

    // ---- per-lane edge (one edge per lane, 32 edges/warp) ----
    int   rIdx = -1, cIdx = -1;
    float dsq  = 0.f;
    {
        int gE = warpE + lane;
        if (gE < E) load_edge(ei, gE, E, is64, nNodes, rIdx, cIdx);
        if (cIdx >= 0) {
            float dx = pos[rIdx * 3 + 0] - pos[cIdx * 3 + 0];
            float dy = pos[rIdx * 3 + 1] - pos[cIdx * 3 + 1];
            float dz = pos[rIdx * 3 + 2] - pos[cIdx * 3 + 2];
            dsq = dx * dx + dy * dy + dz * dz;
            float wp = g_wpos[rIdx];
            atomicAdd(&outpos[(size_t)cIdx * 3 + 0], wp * dx);
            atomicAdd(&outpos[(size_t)cIdx * 3 + 1], wp * dy);
            atomicAdd(&outpos[(size_t)cIdx * 3 + 2], wp * dz);
        }
    }

    int gid = lane >> 2;           // 0..7
    int c   = lane & 3;

    // tile 0: edges 0..15 (lanes 0..15); tile 1: edges 16..31 (lanes 16..31)
    int   rowA0 = __shfl_sync(FULL, rIdx, gid);
    int   colA0 = __shfl_sync(FULL, cIdx, gid);
    float dsqA0 = __shfl_sync(FULL, dsq,  gid);
    int   rowB0 = __shfl_sync(FULL, rIdx, gid + 8);
    int   colB0 = __shfl_sync(FULL, cIdx, gid + 8);
    float dsqB0 = __shfl_sync(FULL, dsq,  gid + 8);
    int   rowA1 = __shfl_sync(FULL, rIdx, gid + 16);
    int   colA1 = __shfl_sync(FULL, cIdx, gid + 16);
    float dsqA1 = __shfl_sync(FULL, dsq,  gid + 16);
    int   rowB1 = __shfl_sync(FULL, rIdx, gid + 24);
    int   colB1 = __shfl_sync(FULL, cIdx, gid + 24);
    float dsqB1 = __shfl_sync(FULL, dsq,  gid + 24);

    const float* w128 = Wx1 + H_DIM * H_DIM;   // row 128 of [129,128]
    bool okA0 = (colA0 >= 0), okB0 = (colB0 >= 0);
    bool okA1 = (colA1 >= 0), okB1 = (colB1 >= 0);
    const float* pAr0 = okA0 ? g_A + (size_t)rowA0 * H_DIM : g_A;
    const float* pAc0 = okA0 ? g_B + (size_t)colA0 * H_DIM : g_B;
    const float* pBr0 = okB0 ? g_A + (size_t)rowB0 * H_DIM : g_A;
    const float* pBc0 = okB0 ? g_B + (size_t)colB0 * H_DIM : g_B;
    const float* pAr1 = okA1 ? g_A + (size_t)rowA1 * H_DIM : g_A;
    const float* pAc1 = okA1 ? g_B + (size_t)colA1 * H_DIM : g_B;
    const float* pBr1 = okB1 ? g_A + (size_t)rowB1 * H_DIM : g_A;
    const float* pBc1 = okB1 ? g_B + (size_t)colB1 * H_DIM : g_B;

    float acc0[8][4], acc1[8][4];
#pragma unroll
    for (int n = 0; n < 8; n++)
#pragma unroll
        for (int q = 0; q < 4; q++) { acc0[n][q] = 0.f; acc1[n][q] = 0.f; }

    __syncthreads();   // sWf ready

    // ---- fused gather + mma ----
#pragma unroll
    for (int j = 0; j < 4; j++) {
        int k0 = c * 32 + 4 * j;
        int k1 = k0 + 16;
        float4 w40 = *(const float4*)(w128 + k0);
        float4 w41 = *(const float4*)(w128 + k1);

        // h[tile][AB][k01][4]
        float hA0_0[4], hA0_1[4], hB0_0[4], hB0_1[4];
        float hA1_0[4], hA1_1[4], hB1_0[4], hB1_1[4];
        gather_h(pAr0, pAc0, dsqA0, okA0, w40, w41, k0, k1, hA0_0, hA0_1);
        gather_h(pBr0, pBc0, dsqB0, okB0, w40, w41, k0, k1, hB0_0, hB0_1);
        gather_h(pAr1, pAc1, dsqA1, okA1, w40, w41, k0, k1, hA1_0, hA1_1);
        gather_h(pBr1, pBc1, dsqB1, okB1, w40, w41, k0, k1, hB1_0, hB1_1);

#pragma unroll
        for (int tt = 0; tt < 4; tt++) {
            int t = 4 * j + tt;
            // tile 0 a-fragments
            float a00 = hA0_0[tt], a01 = hB0_0[tt], a02 = hA0_1[tt], a03 = hB0_1[tt];
            unsigned ah00 = tf32_rnd(a00), ah01 = tf32_rnd(a01);
            unsigned ah02 = tf32_rnd(a02), ah03 = tf32_rnd(a03);
            unsigned al00 = tf32_rnd(a00 - __uint_as_float(ah00));
            unsigned al01 = tf32_rnd(a01 - __uint_as_float(ah01));
            unsigned al02 = tf32_rnd(a02 - __uint_as_float(ah02));
            unsigned al03 = tf32_rnd(a03 - __uint_as_float(ah03));
            // tile 1 a-fragments
            float a10 = hA1_0[tt], a11 = hB1_0[tt], a12 = hA1_1[tt], a13 = hB1_1[tt];
            unsigned ah10 = tf32_rnd(a10), ah11 = tf32_rnd(a11);
            unsigned ah12 = tf32_rnd(a12), ah13 = tf32_rnd(a13);
            unsigned al10 = tf32_rnd(a10 - __uint_as_float(ah10));
            unsigned al11 = tf32_rnd(a11 - __uint_as_float(ah11));
            unsigned al12 = tf32_rnd(a12 - __uint_as_float(ah12));
            unsigned al13 = tf32_rnd(a13 - __uint_as_float(ah13));

            const float4* wrow = sWf + (size_t)t * 8 * 32 + lane;
#pragma unroll
            for (int n = 0; n < 8; n++) {
                float4 b = wrow[n * 32];
                unsigned b0h = __float_as_uint(b.x), b0l = __float_as_uint(b.y);
                unsigned b1h = __float_as_uint(b.z), b1l = __float_as_uint(b.w);
                mma_tf32(acc0[n], ah00, ah01, ah02, ah03, b0h, b1h);
                mma_tf32(acc1[n], ah10, ah11, ah12, ah13, b0h, b1h);
                mma_tf32(acc0[n], al00, al01, al02, al03, b0h, b1h);
                mma_tf32(acc1[n], al10, al11, al12, al13, b0h, b1h);
                mma_tf32(acc0[n], ah00, ah01, ah02, ah03, b0l, b1l);
                mma_tf32(acc1[n], ah10, ah11, ah12, ah13, b0l, b1l);
            }
        }
    }

    // ---- epilogue: pair-transpose via shfl.xor(1), bias, RED.128 scatter ----
    bool evenc = ((c & 1) == 0);
    int  colBase0 = evenc ? (2 * c) : (2 * c - 2);
    int  node0 = evenc ? colA0 : colB0;
    int  node1 = evenc ? colA1 : colB1;
#pragma unroll
    for (int n = 0; n < 8; n++) {
        int colb = n * 8 + colBase0;
        float4 bb = *(const float4*)(bx2 + colb);
        // tile 0
        {
            float o0 = __shfl_xor_sync(FULL, acc0[n][0], 1);
            float o1 = __shfl_xor_sync(FULL, acc0[n][1], 1);
            float o2 = __shfl_xor_sync(FULL, acc0[n][2], 1);
            float o3 = __shfl_xor_sync(FULL, acc0[n][3], 1);
            float4 q;
            if (evenc) q = make_float4(acc0[n][0], acc0[n][1], o0, o1);
            else       q = make_float4(o2, o3, acc0[n][2], acc0[n][3]);
            if (node0 >= 0) {
                float* dst = outx + (size_t)node0 * F_DIM + colb;
                asm volatile("red.global.add.v4.f32 [%0], {%1,%2,%3,%4};"
                             :: "l"(dst),
                                "f"(q.x + bb.x), "f"(q.y + bb.y),
                                "f"(q.z + bb.z), "f"(q.w + bb.w)
                             : "memory");
            }
        }
        // tile 1
        {
            float o0 = __shfl_xor_sync(FULL, acc1[n][0], 1);
            float o1 = __shfl_xor_sync(FULL, acc1[n][1], 1);
            float o2 = __shfl_xor_sync(FULL, acc1[n][2], 1);
            float o3 = __shfl_xor_sync(FULL, acc1[n][3], 1);
            float4 q;
            if (evenc) q = make_float4(acc1[n][0], acc1[n][1], o0, o1);
            else       q = make_float4(o2, o3, acc1[n][2], acc1[n][3]);
            if (node1 >= 0) {
                float* dst = outx + (size_t)node1 * F_DIM + colb;
                asm volatile("red.global.add.v4.f32 [%0], {%1,%2,%3,%4};"
                             :: "l"(dst),
                                "f"(q.x + bb.x), "f"(q.y + bb.y),
                                "f"(q.z + bb.z), "f"(q.w + bb.w)
                             : "memory");
            }
        }
    }
}

// ---------------------------------------------------------------------------
extern "C" void kernel_launch(void* const* d_in, const int* in_sizes, int n_in,
                              void* d_out, int out_size)
{
    const float* x   = (const float*)d_in[0];
    const float* pos = (const float*)d_in[1];
    const void*  ei  = d_in[2];
    const float* Wx1 = (const float*)d_in[3];
    const float* bx1 = (const float*)d_in[4];
    const float* Wx2 = (const float*)d_in[5];
    const float* bx2 = (const float*)d_in[6];
    const float* Wp1 = (const float*)d_in[7];
    const float* bp1 = (const float*)d_in[8];
    const float* Wp2 = (const float*)d_in[9];
    const float* bp2 = (const float*)d_in[10];

    int nNodes = in_sizes[0] / F_DIM;      // 100000
    int E      = in_sizes[2] / 2;          // 1000000

    float* outx   = (float*)d_out;                           // [N, 64]
    float* outpos = (float*)d_out + (size_t)nNodes * F_DIM;  // [N, 3]

    int nCheck = (E < 32) ? E : 32;
    size_t zeroCount = (size_t)nNodes * (F_DIM + 3);

    node_precompute<<<(nNodes + 7) / 8, 128>>>(
        x, Wx1, bx1, Wx2, Wp1, bp1, Wp2, bp2,
        (const long long*)ei, nCheck,
        (float*)d_out, zeroCount, nNodes);

    size_t shmem = sizeof(float4) * 16 * 8 * 32;   // 64 KB
    cudaFuncSetAttribute(edge_kernel, cudaFuncAttributeMaxDynamicSharedMemorySize, (int)shmem);
    edge_kernel<<<(E + 127) / 128, 128, shmem>>>(pos, ei, Wx1, bx2, outx, outpos, E, nNodes);
}

// round 8
// speedup vs baseline: 1.7579x; 1.0858x over previous
#include <cuda_runtime.h>
#include <cstdint>

// ---------------------------------------------------------------------------
// EquivariantMessagePassing — GB300 sm_103a — Round 8
//
//   h_e = silu( A[row] + B[col] + dist_sq * Wx1[128,:] )   (A has bx1 baked in)
//   msg_x_e = h_e @ Wx2 + bx2    -> red.global.add.v4.f32 scatter to out_x[col]
//   pos_upd = wpos[row]*rel_pos  -> atomic scatter to out_pos[col]
// Edge GEMM: mma.sync.m16n8k8.tf32, hi/lo 3-term split.
// R8: g_A/g_B stored PERMUTED (p(k) = j*32+h*16+c*4+q for k = c*32+h*16+4j+q)
// so quad gathers are 64B-contiguous -> gather wavefronts drop 4x.
// ---------------------------------------------------------------------------

#define MAX_N 100000
#define F_DIM 64
#define H_DIM 128

__device__ float  g_A[(size_t)MAX_N * H_DIM];     // 51.2 MB (permuted rows)
__device__ float  g_B[(size_t)MAX_N * H_DIM];     // 51.2 MB (permuted rows)
__device__ float  g_wpos[MAX_N];
__device__ int    g_idx_is64;
__device__ float4 g_Wfrag[16 * 8 * 32];           // [t][n][lane] = (b0hi,b0lo,b1hi,b1lo)
__device__ float  g_w128p[H_DIM];                 // permuted dist_sq weight row

__device__ __forceinline__ float silu_f(float v) {
    return __fdividef(v, 1.0f + __expf(-v));
}

__device__ __forceinline__ unsigned tf32_rnd(float v) {
    unsigned r;
    asm("cvt.rna.tf32.f32 %0, %1;" : "=r"(r) : "f"(v));
    return r;
}

__device__ __forceinline__ void mma_tf32(float acc[4],
                                         unsigned a0, unsigned a1, unsigned a2, unsigned a3,
                                         unsigned b0, unsigned b1) {
    asm volatile(
        "mma.sync.aligned.m16n8k8.row.col.f32.tf32.tf32.f32 "
        "{%0,%1,%2,%3}, {%4,%5,%6,%7}, {%8,%9}, {%0,%1,%2,%3};"
        : "+f"(acc[0]), "+f"(acc[1]), "+f"(acc[2]), "+f"(acc[3])
        : "r"(a0), "r"(a1), "r"(a2), "r"(a3), "r"(b0), "r"(b1));
}

__device__ __forceinline__ void load_edge(const void* ei, int e, int E, int is64,
                                          int nNodes, int& r, int& c)
{
    long long rv, cv;
    if (is64) {
        rv = ((const long long*)ei)[e];
        cv = ((const long long*)ei)[(size_t)E + e];
    } else {
        rv = ((const int*)ei)[e];
        cv = ((const int*)ei)[(size_t)E + e];
    }
    r = (rv >= 0 && rv < nNodes) ? (int)rv : -1;
    c = (cv >= 0 && cv < nNodes) ? (int)cv : -1;
    if (r < 0) c = -1;
}

// permutation: k = c*32 + h*16 + 4j + q  ->  p = j*32 + h*16 + c*4 + q
__device__ __host__ __forceinline__ int permute_k(int k) {
    int c = k >> 5;
    int rem = k & 31;
    int h = rem >> 4;
    int j = (rem >> 2) & 3;
    int q = k & 3;
    return j * 32 + h * 16 + c * 4 + q;
}

// gather + silu for one edge at permuted offsets off0 (h=0) / off1 (h=1)
__device__ __forceinline__ void gather_h(const float* pr, const float* pc,
                                         float dsq, bool ok,
                                         const float4& w40, const float4& w41,
                                         int off0, int off1,
                                         float h0[4], float h1[4])
{
    if (ok) {
        float4 a0 = *(const float4*)(pr + off0);
        float4 b0 = *(const float4*)(pc + off0);
        float4 a1 = *(const float4*)(pr + off1);
        float4 b1 = *(const float4*)(pc + off1);
        h0[0] = silu_f(a0.x + b0.x + dsq * w40.x);
        h0[1] = silu_f(a0.y + b0.y + dsq * w40.y);
        h0[2] = silu_f(a0.z + b0.z + dsq * w40.z);
        h0[3] = silu_f(a0.w + b0.w + dsq * w40.w);
        h1[0] = silu_f(a1.x + b1.x + dsq * w41.x);
        h1[1] = silu_f(a1.y + b1.y + dsq * w41.y);
        h1[2] = silu_f(a1.z + b1.z + dsq * w41.z);
        h1[3] = silu_f(a1.w + b1.w + dsq * w41.w);
    } else {
#pragma unroll
        for (int q = 0; q < 4; q++) { h0[q] = 0.f; h1[q] = 0.f; }
    }
}

// ---------------------------------------------------------------------------
// Kernel 1: per-node precompute + output zeroing + (block 0) prep
// ---------------------------------------------------------------------------
__global__ __launch_bounds__(128) void node_precompute(
    const float* __restrict__ x,
    const float* __restrict__ Wx1, const float* __restrict__ bx1,
    const float* __restrict__ Wx2,
    const float* __restrict__ Wp1, const float* __restrict__ bp1,
    const float* __restrict__ Wp2, const float* __restrict__ bp2,
    const long long* __restrict__ ei, int nCheck,
    float* __restrict__ out0, size_t zeroCount,
    int nNodes)
{
    const int NPB = 8;
    __shared__ float xs[NPB * F_DIM];
    __shared__ float wpart[4][NPB];

    int n0  = blockIdx.x * NPB;
    int tid = threadIdx.x;

    if (blockIdx.x == 0) {
        if (tid == 0) {
            int is64 = 1;
            for (int i = 0; i < nCheck; i++) {
                long long v = ei[i];
                if (v < 0 || v >= (long long)nNodes) { is64 = 0; break; }
            }
            g_idx_is64 = is64;
        }
        // permuted copy of dist_sq weight row
        if (tid < H_DIM)
            g_w128p[permute_k(tid)] = Wx1[H_DIM * H_DIM + tid];
        // Wfrag bake
        for (int i = tid; i < 16 * 8 * 32; i += 128) {
            int lane = i & 31;
            int n    = (i >> 5) & 7;
            int t    = i >> 8;
            int c    = lane & 3;
            int gid  = lane >> 2;
            int col  = n * 8 + gid;
            int k0   = c * 32 + t;
            int k1   = k0 + 16;
            float w0 = Wx2[k0 * F_DIM + col];
            float w1 = Wx2[k1 * F_DIM + col];
            unsigned h0 = tf32_rnd(w0);
            unsigned h1 = tf32_rnd(w1);
            float l0 = w0 - __uint_as_float(h0);
            float l1 = w1 - __uint_as_float(h1);
            g_Wfrag[i] = make_float4(__uint_as_float(h0),
                                     __uint_as_float(tf32_rnd(l0)),
                                     __uint_as_float(h1),
                                     __uint_as_float(tf32_rnd(l1)));
        }
    }

    for (size_t i = (size_t)blockIdx.x * blockDim.x + tid; i < zeroCount;
         i += (size_t)gridDim.x * blockDim.x)
        out0[i] = 0.0f;

    for (int i = tid; i < NPB * F_DIM; i += 128) {
        int node = n0 + (i >> 6);
        xs[i] = (node < nNodes) ? x[(size_t)n0 * F_DIM + i] : 0.0f;
    }
    __syncthreads();

    float accA[NPB], accB[NPB], accP[NPB];
#pragma unroll
    for (int m = 0; m < NPB; m++) { accA[m] = 0.f; accB[m] = 0.f; accP[m] = 0.f; }

    const float* wx1a = Wx1 + tid;
    const float* wx1b = Wx1 + 64 * H_DIM + tid;
    const float* wp1c = Wp1 + tid;

#pragma unroll 4
    for (int k = 0; k < F_DIM; k++) {
        float w1 = wx1a[k * H_DIM];
        float w2 = wx1b[k * H_DIM];
        float wp = wp1c[k * H_DIM];
#pragma unroll
        for (int m = 0; m < NPB; m++) {
            float xv = xs[m * F_DIM + k];
            accA[m] = fmaf(xv, w1, accA[m]);
            accB[m] = fmaf(xv, w2, accB[m]);
            accP[m] = fmaf(xv, wp, accP[m]);
        }
    }

    float b1  = bx1[tid];
    float bp  = bp1[tid];
    float w2v = Wp2[tid];
    int   pt  = permute_k(tid);   // permuted column for A/B stores

#pragma unroll
    for (int m = 0; m < NPB; m++) {
        int node = n0 + m;
        if (node < nNodes) {
            g_A[(size_t)node * H_DIM + pt] = accA[m] + b1;
            g_B[(size_t)node * H_DIM + pt] = accB[m];
        }
        float hv = accP[m] + bp;
        float contrib = silu_f(hv) * w2v;
#pragma unroll
        for (int off = 16; off; off >>= 1)
            contrib += __shfl_xor_sync(0xffffffffu, contrib, off);
        if ((tid & 31) == 0) wpart[tid >> 5][m] = contrib;
    }
    __syncthreads();

    if (tid < NPB) {
        int node = n0 + tid;
        if (node < nNodes)
            g_wpos[node] = wpart[0][tid] + wpart[1][tid] + wpart[2][tid] + wpart[3][tid] + bp2[0];
    }
}

// ---------------------------------------------------------------------------
// Kernel 2: edge kernel. 128 threads (4 warps), 32 edges/warp (two m16 tiles).
// Permuted-layout gathers: per (j,h) a quad reads 64B contiguous.
// ---------------------------------------------------------------------------
__global__ __launch_bounds__(128, 3) void edge_kernel(
    const float* __restrict__ pos,
    const void*  __restrict__ ei,
    const float* __restrict__ bx2,
    float* __restrict__ outx,           // [N, 64]
    float* __restrict__ outpos,         // [N, 3]
    int E, int nNodes)
{
    extern __shared__ float4 sWf[];     // 16*8*32 float4 = 64KB

    const unsigned FULL = 0xffffffffu;
    int tid   = threadIdx.x;
    int lane  = tid & 31;
    int warp  = tid >> 5;
    int warpE = blockIdx.x * 128 + warp * 32;
    int is64  = g_idx_is64;

    // ---- cooperative Wfrag stage (4096 float4 over 128 threads) ----
#pragma unroll
    for (int i = 0; i < 32; i++)
        sWf[i * 128 + tid] = g_Wfrag[i * 128 + tid];

    // ---- per-lane edge (one edge per lane, 32 edges/warp) ----
    int   rIdx = -1, cIdx = -1;
    float dsq  = 0.f;
    {
        int gE = warpE + lane;
        if (gE < E) load_edge(ei, gE, E, is64, nNodes, rIdx, cIdx);
        if (cIdx >= 0) {
            float dx = pos[rIdx * 3 + 0] - pos[cIdx * 3 + 0];
            float dy = pos[rIdx * 3 + 1] - pos[cIdx * 3 + 1];
            float dz = pos[rIdx * 3 + 2] - pos[cIdx * 3 + 2];
            dsq = dx * dx + dy * dy + dz * dz;
            float wp = g_wpos[rIdx];
            atomicAdd(&outpos[(size_t)cIdx * 3 + 0], wp * dx);
            atomicAdd(&outpos[(size_t)cIdx * 3 + 1], wp * dy);
            atomicAdd(&outpos[(size_t)cIdx * 3 + 2], wp * dz);
        }
    }

    int gid = lane >> 2;           // 0..7
    int c   = lane & 3;

    int   rowA0 = __shfl_sync(FULL, rIdx, gid);
    int   colA0 = __shfl_sync(FULL, cIdx, gid);
    float dsqA0 = __shfl_sync(FULL, dsq,  gid);
    int   rowB0 = __shfl_sync(FULL, rIdx, gid + 8);
    int   colB0 = __shfl_sync(FULL, cIdx, gid + 8);
    float dsqB0 = __shfl_sync(FULL, dsq,  gid + 8);
    int   rowA1 = __shfl_sync(FULL, rIdx, gid + 16);
    int   colA1 = __shfl_sync(FULL, cIdx, gid + 16);
    float dsqA1 = __shfl_sync(FULL, dsq,  gid + 16);
    int   rowB1 = __shfl_sync(FULL, rIdx, gid + 24);
    int   colB1 = __shfl_sync(FULL, cIdx, gid + 24);
    float dsqB1 = __shfl_sync(FULL, dsq,  gid + 24);

    bool okA0 = (colA0 >= 0), okB0 = (colB0 >= 0);
    bool okA1 = (colA1 >= 0), okB1 = (colB1 >= 0);
    const float* pAr0 = okA0 ? g_A + (size_t)rowA0 * H_DIM : g_A;
    const float* pAc0 = okA0 ? g_B + (size_t)colA0 * H_DIM : g_B;
    const float* pBr0 = okB0 ? g_A + (size_t)rowB0 * H_DIM : g_A;
    const float* pBc0 = okB0 ? g_B + (size_t)colB0 * H_DIM : g_B;
    const float* pAr1 = okA1 ? g_A + (size_t)rowA1 * H_DIM : g_A;
    const float* pAc1 = okA1 ? g_B + (size_t)colA1 * H_DIM : g_B;
    const float* pBr1 = okB1 ? g_A + (size_t)rowB1 * H_DIM : g_A;
    const float* pBc1 = okB1 ? g_B + (size_t)colB1 * H_DIM : g_B;

    float acc0[8][4], acc1[8][4];
#pragma unroll
    for (int n = 0; n < 8; n++)
#pragma unroll
        for (int q = 0; q < 4; q++) { acc0[n][q] = 0.f; acc1[n][q] = 0.f; }

    __syncthreads();   // sWf ready

    // ---- fused gather + mma (permuted offsets: off0 = j*32 + c*4, off1 = +16) ----
#pragma unroll
    for (int j = 0; j < 4; j++) {
        int off0 = j * 32 + c * 4;
        int off1 = off0 + 16;
        float4 w40 = *(const float4*)(g_w128p + off0);
        float4 w41 = *(const float4*)(g_w128p + off1);

        float hA0_0[4], hA0_1[4], hB0_0[4], hB0_1[4];
        float hA1_0[4], hA1_1[4], hB1_0[4], hB1_1[4];
        gather_h(pAr0, pAc0, dsqA0, okA0, w40, w41, off0, off1, hA0_0, hA0_1);
        gather_h(pBr0, pBc0, dsqB0, okB0, w40, w41, off0, off1, hB0_0, hB0_1);
        gather_h(pAr1, pAc1, dsqA1, okA1, w40, w41, off0, off1, hA1_0, hA1_1);
        gather_h(pBr1, pBc1, dsqB1, okB1, w40, w41, off0, off1, hB1_0, hB1_1);

#pragma unroll
        for (int tt = 0; tt < 4; tt++) {
            int t = 4 * j + tt;
            float a00 = hA0_0[tt], a01 = hB0_0[tt], a02 = hA0_1[tt], a03 = hB0_1[tt];
            unsigned ah00 = tf32_rnd(a00), ah01 = tf32_rnd(a01);
            unsigned ah02 = tf32_rnd(a02), ah03 = tf32_rnd(a03);
            unsigned al00 = tf32_rnd(a00 - __uint_as_float(ah00));
            unsigned al01 = tf32_rnd(a01 - __uint_as_float(ah01));
            unsigned al02 = tf32_rnd(a02 - __uint_as_float(ah02));
            unsigned al03 = tf32_rnd(a03 - __uint_as_float(ah03));
            float a10 = hA1_0[tt], a11 = hB1_0[tt], a12 = hA1_1[tt], a13 = hB1_1[tt];
            unsigned ah10 = tf32_rnd(a10), ah11 = tf32_rnd(a11);
            unsigned ah12 = tf32_rnd(a12), ah13 = tf32_rnd(a13);
            unsigned al10 = tf32_rnd(a10 - __uint_as_float(ah10));
            unsigned al11 = tf32_rnd(a11 - __uint_as_float(ah11));
            unsigned al12 = tf32_rnd(a12 - __uint_as_float(ah12));
            unsigned al13 = tf32_rnd(a13 - __uint_as_float(ah13));

            const float4* wrow = sWf + (size_t)t * 8 * 32 + lane;
#pragma unroll
            for (int n = 0; n < 8; n++) {
                float4 b = wrow[n * 32];
                unsigned b0h = __float_as_uint(b.x), b0l = __float_as_uint(b.y);
                unsigned b1h = __float_as_uint(b.z), b1l = __float_as_uint(b.w);
                mma_tf32(acc0[n], ah00, ah01, ah02, ah03, b0h, b1h);
                mma_tf32(acc1[n], ah10, ah11, ah12, ah13, b0h, b1h);
                mma_tf32(acc0[n], al00, al01, al02, al03, b0h, b1h);
                mma_tf32(acc1[n], al10, al11, al12, al13, b0h, b1h);
                mma_tf32(acc0[n], ah00, ah01, ah02, ah03, b0l, b1l);
                mma_tf32(acc1[n], ah10, ah11, ah12, ah13, b0l, b1l);
            }
        }
    }

    // ---- epilogue: pair-transpose via shfl.xor(1), bias, RED.128 scatter ----
    bool evenc = ((c & 1) == 0);
    int  colBase0 = evenc ? (2 * c) : (2 * c - 2);
    int  node0 = evenc ? colA0 : colB0;
    int  node1 = evenc ? colA1 : colB1;
#pragma unroll
    for (int n = 0; n < 8; n++) {
        int colb = n * 8 + colBase0;
        float4 bb = *(const float4*)(bx2 + colb);
        {
            float o0 = __shfl_xor_sync(FULL, acc0[n][0], 1);
            float o1 = __shfl_xor_sync(FULL, acc0[n][1], 1);
            float o2 = __shfl_xor_sync(FULL, acc0[n][2], 1);
            float o3 = __shfl_xor_sync(FULL, acc0[n][3], 1);
            float4 q;
            if (evenc) q = make_float4(acc0[n][0], acc0[n][1], o0, o1);
            else       q = make_float4(o2, o3, acc0[n][2], acc0[n][3]);
            if (node0 >= 0) {
                float* dst = outx + (size_t)node0 * F_DIM + colb;
                asm volatile("red.global.add.v4.f32 [%0], {%1,%2,%3,%4};"
                             :: "l"(dst),
                                "f"(q.x + bb.x), "f"(q.y + bb.y),
                                "f"(q.z + bb.z), "f"(q.w + bb.w)
                             : "memory");
            }
        }
        {
            float o0 = __shfl_xor_sync(FULL, acc1[n][0], 1);
            float o1 = __shfl_xor_sync(FULL, acc1[n][1], 1);
            float o2 = __shfl_xor_sync(FULL, acc1[n][2], 1);
            float o3 = __shfl_xor_sync(FULL, acc1[n][3], 1);
            float4 q;
            if (evenc) q = make_float4(acc1[n][0], acc1[n][1], o0, o1);
            else       q = make_float4(o2, o3, acc1[n][2], acc1[n][3]);
            if (node1 >= 0) {
                float* dst = outx + (size_t)node1 * F_DIM + colb;
                asm volatile("red.global.add.v4.f32 [%0], {%1,%2,%3,%4};"
                             :: "l"(dst),
                                "f"(q.x + bb.x), "f"(q.y + bb.y),
                                "f"(q.z + bb.z), "f"(q.w + bb.w)
                             : "memory");
            }
        }
    }
}

// ---------------------------------------------------------------------------
extern "C" void kernel_launch(void* const* d_in, const int* in_sizes, int n_in,
                              void* d_out, int out_size)
{
    const float* x   = (const float*)d_in[0];
    const float* pos = (const float*)d_in[1];
    const void*  ei  = d_in[2];
    const float* Wx1 = (const float*)d_in[3];
    const float* bx1 = (const float*)d_in[4];
    const float* Wx2 = (const float*)d_in[5];
    const float* bx2 = (const float*)d_in[6];
    const float* Wp1 = (const float*)d_in[7];
    const float* bp1 = (const float*)d_in[8];
    const float* Wp2 = (const float*)d_in[9];
    const float* bp2 = (const float*)d_in[10];

    int nNodes = in_sizes[0] / F_DIM;      // 100000
    int E      = in_sizes[2] / 2;          // 1000000

    float* outx   = (float*)d_out;                           // [N, 64]
    float* outpos = (float*)d_out + (size_t)nNodes * F_DIM;  // [N, 3]

    int nCheck = (E < 32) ? E : 32;
    size_t zeroCount = (size_t)nNodes * (F_DIM + 3);

    node_precompute<<<(nNodes + 7) / 8, 128>>>(
        x, Wx1, bx1, Wx2, Wp1, bp1, Wp2, bp2,
        (const long long*)ei, nCheck,
        (float*)d_out, zeroCount, nNodes);

    size_t shmem = sizeof(float4) * 16 * 8 * 32;   // 64 KB
    cudaFuncSetAttribute(edge_kernel, cudaFuncAttributeMaxDynamicSharedMemorySize, (int)shmem);
    edge_kernel<<<(E + 127) / 128, 128, shmem>>>(pos, ei, bx2, outx, outpos, E, nNodes);
}

// round 9
// speedup vs baseline: 2.1226x; 1.2075x over previous
#include <cuda_runtime.h>
#include <cstdint>

// ---------------------------------------------------------------------------
// EquivariantMessagePassing — GB300 sm_103a — Round 9
//
//   h_e = silu( A[row] + B[col] + dist_sq * Wx1[128,:] )   (A has bx1 baked in)
//   msg_x_e = h_e @ Wx2 + bx2    -> red.global.add.v4.f32 scatter to out_x[col]
//   pos_upd = wpos[row]*rel_pos  -> atomic scatter to out_pos[col]
// Edge GEMM: mma.sync.m16n8k8.tf32, 2-term split (a_hi+a_lo)·b_hi = a·b_hi.
// R9: Wfrag float2 (32KB smem), 4 blocks/SM (16 warps), MMA count -33%.
// Permuted g_A/g_B layout (p(k)=j*32+h*16+c*4+q) for contiguous quad gathers.
// ---------------------------------------------------------------------------

#define MAX_N 100000
#define F_DIM 64
#define H_DIM 128

__device__ float  g_A[(size_t)MAX_N * H_DIM];     // 51.2 MB (permuted rows)
__device__ float  g_B[(size_t)MAX_N * H_DIM];     // 51.2 MB (permuted rows)
__device__ float  g_wpos[MAX_N];
__device__ int    g_idx_is64;
__device__ float2 g_Wfrag[16 * 8 * 32];           // [t][n][lane] = (b0hi, b1hi)
__device__ float  g_w128p[H_DIM];                 // permuted dist_sq weight row

__device__ __forceinline__ float silu_f(float v) {
    return __fdividef(v, 1.0f + __expf(-v));
}

__device__ __forceinline__ unsigned tf32_rnd(float v) {
    unsigned r;
    asm("cvt.rna.tf32.f32 %0, %1;" : "=r"(r) : "f"(v));
    return r;
}

__device__ __forceinline__ void mma_tf32(float acc[4],
                                         unsigned a0, unsigned a1, unsigned a2, unsigned a3,
                                         unsigned b0, unsigned b1) {
    asm volatile(
        "mma.sync.aligned.m16n8k8.row.col.f32.tf32.tf32.f32 "
        "{%0,%1,%2,%3}, {%4,%5,%6,%7}, {%8,%9}, {%0,%1,%2,%3};"
        : "+f"(acc[0]), "+f"(acc[1]), "+f"(acc[2]), "+f"(acc[3])
        : "r"(a0), "r"(a1), "r"(a2), "r"(a3), "r"(b0), "r"(b1));
}

__device__ __forceinline__ void load_edge(const void* ei, int e, int E, int is64,
                                          int nNodes, int& r, int& c)
{
    long long rv, cv;
    if (is64) {
        rv = ((const long long*)ei)[e];
        cv = ((const long long*)ei)[(size_t)E + e];
    } else {
        rv = ((const int*)ei)[e];
        cv = ((const int*)ei)[(size_t)E + e];
    }
    r = (rv >= 0 && rv < nNodes) ? (int)rv : -1;
    c = (cv >= 0 && cv < nNodes) ? (int)cv : -1;
    if (r < 0) c = -1;
}

// permutation: k = c*32 + h*16 + 4j + q  ->  p = j*32 + h*16 + c*4 + q
__device__ __host__ __forceinline__ int permute_k(int k) {
    int c = k >> 5;
    int rem = k & 31;
    int h = rem >> 4;
    int j = (rem >> 2) & 3;
    int q = k & 3;
    return j * 32 + h * 16 + c * 4 + q;
}

// gather + silu for one edge at permuted offsets off0 (h=0) / off1 (h=1)
__device__ __forceinline__ void gather_h(const float* pr, const float* pc,
                                         float dsq, bool ok,
                                         const float4& w40, const float4& w41,
                                         int off0, int off1,
                                         float h0[4], float h1[4])
{
    if (ok) {
        float4 a0 = *(const float4*)(pr + off0);
        float4 b0 = *(const float4*)(pc + off0);
        float4 a1 = *(const float4*)(pr + off1);
        float4 b1 = *(const float4*)(pc + off1);
        h0[0] = silu_f(a0.x + b0.x + dsq * w40.x);
        h0[1] = silu_f(a0.y + b0.y + dsq * w40.y);
        h0[2] = silu_f(a0.z + b0.z + dsq * w40.z);
        h0[3] = silu_f(a0.w + b0.w + dsq * w40.w);
        h1[0] = silu_f(a1.x + b1.x + dsq * w41.x);
        h1[1] = silu_f(a1.y + b1.y + dsq * w41.y);
        h1[2] = silu_f(a1.z + b1.z + dsq * w41.z);
        h1[3] = silu_f(a1.w + b1.w + dsq * w41.w);
    } else {
#pragma unroll
        for (int q = 0; q < 4; q++) { h0[q] = 0.f; h1[q] = 0.f; }
    }
}

// ---------------------------------------------------------------------------
// Kernel 1: per-node precompute + output zeroing + (block 0) prep
// ---------------------------------------------------------------------------
__global__ __launch_bounds__(128) void node_precompute(
    const float* __restrict__ x,
    const float* __restrict__ Wx1, const float* __restrict__ bx1,
    const float* __restrict__ Wx2,
    const float* __restrict__ Wp1, const float* __restrict__ bp1,
    const float* __restrict__ Wp2, const float* __restrict__ bp2,
    const long long* __restrict__ ei, int nCheck,
    float* __restrict__ out0, size_t zeroCount,
    int nNodes)
{
    const int NPB = 8;
    __shared__ float xs[NPB * F_DIM];
    __shared__ float wpart[4][NPB];

    int n0  = blockIdx.x * NPB;
    int tid = threadIdx.x;

    if (blockIdx.x == 0) {
        if (tid == 0) {
            int is64 = 1;
            for (int i = 0; i < nCheck; i++) {
                long long v = ei[i];
                if (v < 0 || v >= (long long)nNodes) { is64 = 0; break; }
            }
            g_idx_is64 = is64;
        }
        // permuted copy of dist_sq weight row
        if (tid < H_DIM)
            g_w128p[permute_k(tid)] = Wx1[H_DIM * H_DIM + tid];
        // Wfrag bake (hi parts only — 2-term split)
        for (int i = tid; i < 16 * 8 * 32; i += 128) {
            int lane = i & 31;
            int n    = (i >> 5) & 7;
            int t    = i >> 8;
            int c    = lane & 3;
            int gid  = lane >> 2;
            int col  = n * 8 + gid;
            int k0   = c * 32 + t;
            int k1   = k0 + 16;
            unsigned h0 = tf32_rnd(Wx2[k0 * F_DIM + col]);
            unsigned h1 = tf32_rnd(Wx2[k1 * F_DIM + col]);
            g_Wfrag[i] = make_float2(__uint_as_float(h0), __uint_as_float(h1));
        }
    }

    for (size_t i = (size_t)blockIdx.x * blockDim.x + tid; i < zeroCount;
         i += (size_t)gridDim.x * blockDim.x)
        out0[i] = 0.0f;

    for (int i = tid; i < NPB * F_DIM; i += 128) {
        int node = n0 + (i >> 6);
        xs[i] = (node < nNodes) ? x[(size_t)n0 * F_DIM + i] : 0.0f;
    }
    __syncthreads();

    float accA[NPB], accB[NPB], accP[NPB];
#pragma unroll
    for (int m = 0; m < NPB; m++) { accA[m] = 0.f; accB[m] = 0.f; accP[m] = 0.f; }

    const float* wx1a = Wx1 + tid;
    const float* wx1b = Wx1 + 64 * H_DIM + tid;
    const float* wp1c = Wp1 + tid;

#pragma unroll 4
    for (int k = 0; k < F_DIM; k++) {
        float w1 = wx1a[k * H_DIM];
        float w2 = wx1b[k * H_DIM];
        float wp = wp1c[k * H_DIM];
#pragma unroll
        for (int m = 0; m < NPB; m++) {
            float xv = xs[m * F_DIM + k];
            accA[m] = fmaf(xv, w1, accA[m]);
            accB[m] = fmaf(xv, w2, accB[m]);
            accP[m] = fmaf(xv, wp, accP[m]);
        }
    }

    float b1  = bx1[tid];
    float bp  = bp1[tid];
    float w2v = Wp2[tid];
    int   pt  = permute_k(tid);   // permuted column for A/B stores

#pragma unroll
    for (int m = 0; m < NPB; m++) {
        int node = n0 + m;
        if (node < nNodes) {
            g_A[(size_t)node * H_DIM + pt] = accA[m] + b1;
            g_B[(size_t)node * H_DIM + pt] = accB[m];
        }
        float hv = accP[m] + bp;
        float contrib = silu_f(hv) * w2v;
#pragma unroll
        for (int off = 16; off; off >>= 1)
            contrib += __shfl_xor_sync(0xffffffffu, contrib, off);
        if ((tid & 31) == 0) wpart[tid >> 5][m] = contrib;
    }
    __syncthreads();

    if (tid < NPB) {
        int node = n0 + tid;
        if (node < nNodes)
            g_wpos[node] = wpart[0][tid] + wpart[1][tid] + wpart[2][tid] + wpart[3][tid] + bp2[0];
    }
}

// ---------------------------------------------------------------------------
// Kernel 2: edge kernel. 128 threads (4 warps), 32 edges/warp (two m16 tiles),
// 4 blocks/SM. 2-term tf32 split, float2 Wfrag in 32KB smem.
// ---------------------------------------------------------------------------
__global__ __launch_bounds__(128, 4) void edge_kernel(
    const float* __restrict__ pos,
    const void*  __restrict__ ei,
    const float* __restrict__ bx2,
    float* __restrict__ outx,           // [N, 64]
    float* __restrict__ outpos,         // [N, 3]
    int E, int nNodes)
{
    extern __shared__ float2 sWf[];     // 16*8*32 float2 = 32KB

    const unsigned FULL = 0xffffffffu;
    int tid   = threadIdx.x;
    int lane  = tid & 31;
    int warp  = tid >> 5;
    int warpE = blockIdx.x * 128 + warp * 32;
    int is64  = g_idx_is64;

    // ---- cooperative Wfrag stage (4096 float2 over 128 threads) ----
#pragma unroll
    for (int i = 0; i < 32; i++)
        sWf[i * 128 + tid] = g_Wfrag[i * 128 + tid];

    // ---- per-lane edge (one edge per lane, 32 edges/warp) ----
    int   rIdx = -1, cIdx = -1;
    float dsq  = 0.f;
    {
        int gE = warpE + lane;
        if (gE < E) load_edge(ei, gE, E, is64, nNodes, rIdx, cIdx);
        if (cIdx >= 0) {
            float dx = pos[rIdx * 3 + 0] - pos[cIdx * 3 + 0];
            float dy = pos[rIdx * 3 + 1] - pos[cIdx * 3 + 1];
            float dz = pos[rIdx * 3 + 2] - pos[cIdx * 3 + 2];
            dsq = dx * dx + dy * dy + dz * dz;
            float wp = g_wpos[rIdx];
            atomicAdd(&outpos[(size_t)cIdx * 3 + 0], wp * dx);
            atomicAdd(&outpos[(size_t)cIdx * 3 + 1], wp * dy);
            atomicAdd(&outpos[(size_t)cIdx * 3 + 2], wp * dz);
        }
    }

    int gid = lane >> 2;           // 0..7
    int c   = lane & 3;

    int   rowA0 = __shfl_sync(FULL, rIdx, gid);
    int   colA0 = __shfl_sync(FULL, cIdx, gid);
    float dsqA0 = __shfl_sync(FULL, dsq,  gid);
    int   rowB0 = __shfl_sync(FULL, rIdx, gid + 8);
    int   colB0 = __shfl_sync(FULL, cIdx, gid + 8);
    float dsqB0 = __shfl_sync(FULL, dsq,  gid + 8);
    int   rowA1 = __shfl_sync(FULL, rIdx, gid + 16);
    int   colA1 = __shfl_sync(FULL, cIdx, gid + 16);
    float dsqA1 = __shfl_sync(FULL, dsq,  gid + 16);
    int   rowB1 = __shfl_sync(FULL, rIdx, gid + 24);
    int   colB1 = __shfl_sync(FULL, cIdx, gid + 24);
    float dsqB1 = __shfl_sync(FULL, dsq,  gid + 24);

    bool okA0 = (colA0 >= 0), okB0 = (colB0 >= 0);
    bool okA1 = (colA1 >= 0), okB1 = (colB1 >= 0);
    const float* pAr0 = okA0 ? g_A + (size_t)rowA0 * H_DIM : g_A;
    const float* pAc0 = okA0 ? g_B + (size_t)colA0 * H_DIM : g_B;
    const float* pBr0 = okB0 ? g_A + (size_t)rowB0 * H_DIM : g_A;
    const float* pBc0 = okB0 ? g_B + (size_t)colB0 * H_DIM : g_B;
    const float* pAr1 = okA1 ? g_A + (size_t)rowA1 * H_DIM : g_A;
    const float* pAc1 = okA1 ? g_B + (size_t)colA1 * H_DIM : g_B;
    const float* pBr1 = okB1 ? g_A + (size_t)rowB1 * H_DIM : g_A;
    const float* pBc1 = okB1 ? g_B + (size_t)colB1 * H_DIM : g_B;

    float acc0[8][4], acc1[8][4];
#pragma unroll
    for (int n = 0; n < 8; n++)
#pragma unroll
        for (int q = 0; q < 4; q++) { acc0[n][q] = 0.f; acc1[n][q] = 0.f; }

    __syncthreads();   // sWf ready

    // ---- fused gather + mma (permuted offsets: off0 = j*32 + c*4, off1 = +16) ----
#pragma unroll
    for (int j = 0; j < 4; j++) {
        int off0 = j * 32 + c * 4;
        int off1 = off0 + 16;
        float4 w40 = *(const float4*)(g_w128p + off0);
        float4 w41 = *(const float4*)(g_w128p + off1);

        float hA0_0[4], hA0_1[4], hB0_0[4], hB0_1[4];
        float hA1_0[4], hA1_1[4], hB1_0[4], hB1_1[4];
        gather_h(pAr0, pAc0, dsqA0, okA0, w40, w41, off0, off1, hA0_0, hA0_1);
        gather_h(pBr0, pBc0, dsqB0, okB0, w40, w41, off0, off1, hB0_0, hB0_1);
        gather_h(pAr1, pAc1, dsqA1, okA1, w40, w41, off0, off1, hA1_0, hA1_1);
        gather_h(pBr1, pBc1, dsqB1, okB1, w40, w41, off0, off1, hB1_0, hB1_1);

#pragma unroll
        for (int tt = 0; tt < 4; tt++) {
            int t = 4 * j + tt;
            // tile 0 a-fragments (hi + lo of a; b stays hi-only)
            float a00 = hA0_0[tt], a01 = hB0_0[tt], a02 = hA0_1[tt], a03 = hB0_1[tt];
            unsigned ah00 = tf32_rnd(a00), ah01 = tf32_rnd(a01);
            unsigned ah02 = tf32_rnd(a02), ah03 = tf32_rnd(a03);
            unsigned al00 = tf32_rnd(a00 - __uint_as_float(ah00));
            unsigned al01 = tf32_rnd(a01 - __uint_as_float(ah01));
            unsigned al02 = tf32_rnd(a02 - __uint_as_float(ah02));
            unsigned al03 = tf32_rnd(a03 - __uint_as_float(ah03));
            // tile 1 a-fragments
            float a10 = hA1_0[tt], a11 = hB1_0[tt], a12 = hA1_1[tt], a13 = hB1_1[tt];
            unsigned ah10 = tf32_rnd(a10), ah11 = tf32_rnd(a11);
            unsigned ah12 = tf32_rnd(a12), ah13 = tf32_rnd(a13);
            unsigned al10 = tf32_rnd(a10 - __uint_as_float(ah10));
            unsigned al11 = tf32_rnd(a11 - __uint_as_float(ah11));
            unsigned al12 = tf32_rnd(a12 - __uint_as_float(ah12));
            unsigned al13 = tf32_rnd(a13 - __uint_as_float(ah13));

            const float2* wrow = sWf + (size_t)t * 8 * 32 + lane;
#pragma unroll
            for (int n = 0; n < 8; n++) {
                float2 b = wrow[n * 32];
                unsigned b0h = __float_as_uint(b.x);
                unsigned b1h = __float_as_uint(b.y);
                mma_tf32(acc0[n], ah00, ah01, ah02, ah03, b0h, b1h);
                mma_tf32(acc1[n], ah10, ah11, ah12, ah13, b0h, b1h);
                mma_tf32(acc0[n], al00, al01, al02, al03, b0h, b1h);
                mma_tf32(acc1[n], al10, al11, al12, al13, b0h, b1h);
            }
        }
    }

    // ---- epilogue: pair-transpose via shfl.xor(1), bias, RED.128 scatter ----
    bool evenc = ((c & 1) == 0);
    int  colBase0 = evenc ? (2 * c) : (2 * c - 2);
    int  node0 = evenc ? colA0 : colB0;
    int  node1 = evenc ? colA1 : colB1;
#pragma unroll
    for (int n = 0; n < 8; n++) {
        int colb = n * 8 + colBase0;
        float4 bb = *(const float4*)(bx2 + colb);
        {
            float o0 = __shfl_xor_sync(FULL, acc0[n][0], 1);
            float o1 = __shfl_xor_sync(FULL, acc0[n][1], 1);
            float o2 = __shfl_xor_sync(FULL, acc0[n][2], 1);
            float o3 = __shfl_xor_sync(FULL, acc0[n][3], 1);
            float4 q;
            if (evenc) q = make_float4(acc0[n][0], acc0[n][1], o0, o1);
            else       q = make_float4(o2, o3, acc0[n][2], acc0[n][3]);
            if (node0 >= 0) {
                float* dst = outx + (size_t)node0 * F_DIM + colb;
                asm volatile("red.global.add.v4.f32 [%0], {%1,%2,%3,%4};"
                             :: "l"(dst),
                                "f"(q.x + bb.x), "f"(q.y + bb.y),
                                "f"(q.z + bb.z), "f"(q.w + bb.w)
                             : "memory");
            }
        }
        {
            float o0 = __shfl_xor_sync(FULL, acc1[n][0], 1);
            float o1 = __shfl_xor_sync(FULL, acc1[n][1], 1);
            float o2 = __shfl_xor_sync(FULL, acc1[n][2], 1);
            float o3 = __shfl_xor_sync(FULL, acc1[n][3], 1);
            float4 q;
            if (evenc) q = make_float4(acc1[n][0], acc1[n][1], o0, o1);
            else       q = make_float4(o2, o3, acc1[n][2], acc1[n][3]);
            if (node1 >= 0) {
                float* dst = outx + (size_t)node1 * F_DIM + colb;
                asm volatile("red.global.add.v4.f32 [%0], {%1,%2,%3,%4};"
                             :: "l"(dst),
                                "f"(q.x + bb.x), "f"(q.y + bb.y),
                                "f"(q.z + bb.z), "f"(q.w + bb.w)
                             : "memory");
            }
        }
    }
}

// ---------------------------------------------------------------------------
extern "C" void kernel_launch(void* const* d_in, const int* in_sizes, int n_in,
                              void* d_out, int out_size)
{
    const float* x   = (const float*)d_in[0];
    const float* pos = (const float*)d_in[1];
    const void*  ei  = d_in[2];
    const float* Wx1 = (const float*)d_in[3];
    const float* bx1 = (const float*)d_in[4];
    const float* Wx2 = (const float*)d_in[5];
    const float* bx2 = (const float*)d_in[6];
    const float* Wp1 = (const float*)d_in[7];
    const float* bp1 = (const float*)d_in[8];
    const float* Wp2 = (const float*)d_in[9];
    const float* bp2 = (const float*)d_in[10];

    int nNodes = in_sizes[0] / F_DIM;      // 100000
    int E      = in_sizes[2] / 2;          // 1000000

    float* outx   = (float*)d_out;                           // [N, 64]
    float* outpos = (float*)d_out + (size_t)nNodes * F_DIM;  // [N, 3]

    int nCheck = (E < 32) ? E : 32;
    size_t zeroCount = (size_t)nNodes * (F_DIM + 3);

    node_precompute<<<(nNodes + 7) / 8, 128>>>(
        x, Wx1, bx1, Wx2, Wp1, bp1, Wp2, bp2,
        (const long long*)ei, nCheck,
        (float*)d_out, zeroCount, nNodes);

    size_t shmem = sizeof(float2) * 16 * 8 * 32;   // 32 KB
    cudaFuncSetAttribute(edge_kernel, cudaFuncAttributeMaxDynamicSharedMemorySize, (int)shmem);
    edge_kernel<<<(E + 127) / 128, 128, shmem>>>(pos, ei, bx2, outx, outpos, E, nNodes);
}